// round 14
// baseline (speedup 1.0000x reference)
#include <cuda_runtime.h>
#include <cuda_bf16.h>
#include <math.h>
#include <stdint.h>

#define BGR   128
#define NODES 4096
#define HID   256
#define TYPED 100
#define NLAY  4
#define NTILE 1024

#if defined(__CUDA_ARCH_FEAT_SM103_ALL) || defined(__CUDA_ARCH_FEAT_SM100_ALL) || defined(__CUDA_ARCH_SPECIFIC__) || defined(__CUDA_ARCH_FAMILY_SPECIFIC__)
#define HAS_TC 1
#else
#define HAS_TC 0
#endif

__device__ float g_feat[NODES * 384];
__device__ float g_nf  [NODES * HID];
__device__ float g_h   [NODES * HID];
__device__ float g_PiQ [NODES * HID];
__device__ float g_PjT [BGR * HID * 32];
__device__ float g_gf  [BGR * HID];
__device__ float g_qb  [NLAY * BGR * HID];
__device__ __nv_bfloat16 g_efT [(size_t)NTILE * 128 * 64];
__device__ __nv_bfloat16 g_W1T [NLAY * 256 * 64];
__device__ __nv_bfloat16 g_WB  [96 * 16384];
__device__ __nv_bfloat16 g_nfT [NODES * HID];
__device__ __nv_bfloat16 g_msgT[NODES * HID];

typedef unsigned long long ull;

__device__ __forceinline__ float silu_f(float x) { return x / (1.0f + __expf(-x)); }
__device__ __forceinline__ float silu_t(float x) {
    float xh = 0.5f * x, t;
    asm("tanh.approx.f32 %0, %1;" : "=f"(t) : "f"(xh));
    return fmaf(xh, t, xh);
}
__device__ __forceinline__ ull pack_dup(float f) { ull r; asm("mov.b64 %0, {%1,%1};" : "=l"(r) : "f"(f)); return r; }
__device__ __forceinline__ void unpack2(ull v, float& lo, float& hi) { asm("mov.b64 {%0,%1}, %2;" : "=f"(lo), "=f"(hi) : "l"(v)); }
__device__ __forceinline__ void fma2(ull& a, ull x, ull y) { asm("fma.rn.f32x2 %0, %1, %2, %0;" : "+l"(a) : "l"(x), "l"(y)); }
__device__ __forceinline__ void cp16(void* sdst, const void* gsrc) {
    unsigned s = (unsigned)__cvta_generic_to_shared(sdst);
    asm volatile("cp.async.cg.shared.global [%0], [%1], 16;" :: "r"(s), "l"(gsrc));
}
__device__ __forceinline__ void cp_commit() { asm volatile("cp.async.commit_group;"); }
template<int N> __device__ __forceinline__ void cp_wait() { asm volatile("cp.async.wait_group %0;" :: "n"(N)); }
__device__ __forceinline__ uint32_t smu32(const void* p) { return (uint32_t)__cvta_generic_to_shared(p); }
__device__ __forceinline__ void mbar_init(uint32_t a, uint32_t c) {
    asm volatile("mbarrier.init.shared.b64 [%0], %1;" :: "r"(a), "r"(c) : "memory");
}
__device__ __forceinline__ void mbar_wait(uint32_t a, uint32_t ph) {
    asm volatile("{\n\t.reg .pred P;\nWL%=:\n\t"
        "mbarrier.try_wait.parity.acquire.cta.shared::cta.b64 P, [%0], %1, 0x989680;\n\t"
        "@!P bra WL%=;\n\t}" :: "r"(a), "r"(ph) : "memory");
}
__device__ __forceinline__ void fence_pa() { asm volatile("fence.proxy.async.shared::cta;" ::: "memory"); }
__device__ __forceinline__ uint32_t sw128(uint32_t b) { return b ^ ((b >> 3) & 0x70); }

#define TILE_WR(base, node, c, val) \
    *(__nv_bfloat16*)((char*)(base) + (size_t)((((node) >> 7) << 2) + ((c) >> 6)) * 16384 \
        + sw128((uint32_t)((((node) & 127) << 7) + (((c) & 63) << 1)))) = (val)

#if HAS_TC
__device__ __forceinline__ void tcf_b() { asm volatile("tcgen05.fence::before_thread_sync;" ::: "memory"); }
__device__ __forceinline__ void tcf_a() { asm volatile("tcgen05.fence::after_thread_sync;" ::: "memory"); }
__device__ __forceinline__ void tcw_ld() { asm volatile("tcgen05.wait::ld.sync.aligned;" ::: "memory"); }
__device__ __forceinline__ void tcw_st() { asm volatile("tcgen05.wait::st.sync.aligned;" ::: "memory"); }
__device__ __forceinline__ void tc_commit(uint32_t b) {
    asm volatile("tcgen05.commit.cta_group::1.mbarrier::arrive::one.shared::cluster.b64 [%0];" :: "r"(b) : "memory");
}
#define TC_LD_X64(r, a) \
    asm volatile("tcgen05.ld.sync.aligned.32x32b.x64.b32 " \
        "{%0,%1,%2,%3,%4,%5,%6,%7,%8,%9,%10,%11,%12,%13,%14,%15," \
        "%16,%17,%18,%19,%20,%21,%22,%23,%24,%25,%26,%27,%28,%29,%30,%31," \
        "%32,%33,%34,%35,%36,%37,%38,%39,%40,%41,%42,%43,%44,%45,%46,%47," \
        "%48,%49,%50,%51,%52,%53,%54,%55,%56,%57,%58,%59,%60,%61,%62,%63}, [%64];" \
        : "=r"((r)[0]),"=r"((r)[1]),"=r"((r)[2]),"=r"((r)[3]),"=r"((r)[4]),"=r"((r)[5]),"=r"((r)[6]),"=r"((r)[7]), \
          "=r"((r)[8]),"=r"((r)[9]),"=r"((r)[10]),"=r"((r)[11]),"=r"((r)[12]),"=r"((r)[13]),"=r"((r)[14]),"=r"((r)[15]), \
          "=r"((r)[16]),"=r"((r)[17]),"=r"((r)[18]),"=r"((r)[19]),"=r"((r)[20]),"=r"((r)[21]),"=r"((r)[22]),"=r"((r)[23]), \
          "=r"((r)[24]),"=r"((r)[25]),"=r"((r)[26]),"=r"((r)[27]),"=r"((r)[28]),"=r"((r)[29]),"=r"((r)[30]),"=r"((r)[31]), \
          "=r"((r)[32]),"=r"((r)[33]),"=r"((r)[34]),"=r"((r)[35]),"=r"((r)[36]),"=r"((r)[37]),"=r"((r)[38]),"=r"((r)[39]), \
          "=r"((r)[40]),"=r"((r)[41]),"=r"((r)[42]),"=r"((r)[43]),"=r"((r)[44]),"=r"((r)[45]),"=r"((r)[46]),"=r"((r)[47]), \
          "=r"((r)[48]),"=r"((r)[49]),"=r"((r)[50]),"=r"((r)[51]),"=r"((r)[52]),"=r"((r)[53]),"=r"((r)[54]),"=r"((r)[55]), \
          "=r"((r)[56]),"=r"((r)[57]),"=r"((r)[58]),"=r"((r)[59]),"=r"((r)[60]),"=r"((r)[61]),"=r"((r)[62]),"=r"((r)[63]) \
        : "r"(a))
#define TC_ST_X32(a, r) \
    asm volatile("tcgen05.st.sync.aligned.32x32b.x32.b32 [%0], " \
        "{%1,%2,%3,%4,%5,%6,%7,%8,%9,%10,%11,%12,%13,%14,%15,%16," \
        "%17,%18,%19,%20,%21,%22,%23,%24,%25,%26,%27,%28,%29,%30,%31,%32};" \
        :: "r"(a), \
           "r"((r)[0]),"r"((r)[1]),"r"((r)[2]),"r"((r)[3]),"r"((r)[4]),"r"((r)[5]),"r"((r)[6]),"r"((r)[7]), \
           "r"((r)[8]),"r"((r)[9]),"r"((r)[10]),"r"((r)[11]),"r"((r)[12]),"r"((r)[13]),"r"((r)[14]),"r"((r)[15]), \
           "r"((r)[16]),"r"((r)[17]),"r"((r)[18]),"r"((r)[19]),"r"((r)[20]),"r"((r)[21]),"r"((r)[22]),"r"((r)[23]), \
           "r"((r)[24]),"r"((r)[25]),"r"((r)[26]),"r"((r)[27]),"r"((r)[28]),"r"((r)[29]),"r"((r)[30]),"r"((r)[31]) \
        : "memory")
#define IDESC_BF16 0x8400490u
#define IDESC_BF16_N128 0x8200490u
__device__ __forceinline__ void mma_f16_ss(uint32_t d, uint64_t a, uint64_t b, bool en) {
    uint32_t e = en ? 1u : 0u;
    asm volatile("{\n\t.reg .pred p;\n\tsetp.ne.u32 p, %5, 0;\n\t"
        "tcgen05.mma.cta_group::1.kind::f16 [%0], %1, %2, %3, {%4,%4,%4,%4}, p;\n\t}"
        :: "r"(d), "l"(a), "l"(b), "r"(IDESC_BF16), "r"(0u), "r"(e) : "memory");
}
__device__ __forceinline__ void mma_f16_ts_n(uint32_t d, uint32_t a, uint64_t b, uint32_t idesc, bool en) {
    uint32_t e = en ? 1u : 0u;
    asm volatile("{\n\t.reg .pred p;\n\tsetp.ne.u32 p, %5, 0;\n\t"
        "tcgen05.mma.cta_group::1.kind::f16 [%0], [%1], %2, %3, {%4,%4,%4,%4}, p;\n\t}"
        :: "r"(d), "r"(a), "l"(b), "r"(idesc), "r"(0u), "r"(e) : "memory");
}
__device__ __forceinline__ void mma_f16_ts(uint32_t d, uint32_t a, uint64_t b, bool en) {
    mma_f16_ts_n(d, a, b, IDESC_BF16, en);
}
__device__ __forceinline__ uint64_t mk_desc(const void* p) {
    return 0x4000404000010000ULL | (ull)((smu32(p) >> 4) & 0x3FFF);
}
#endif

// ---------- generic fp32 GEMM (FFMA2); optional bf16-tile mirror ----------
#define GBM 64
#define GBN 64
#define GBK 16
__global__ void __launch_bounds__(256) gemm_kernel(
    const float* __restrict__ A0, int K0, const float* __restrict__ A1, int K1,
    const float* __restrict__ W, int ldw, const float* __restrict__ bias,
    float* __restrict__ C, int ldc, int M, int N, int mode,
    __nv_bfloat16* __restrict__ outT)
{
    __shared__ float As[GBK][GBM + 2];
    __shared__ float Wsm[GBK][GBN];
    const int tid = threadIdx.x, tx = tid & 15, ty = tid >> 4;
    const int row0 = blockIdx.x * GBM, col0 = blockIdx.y * GBN;
    const int K = K0 + K1;
    ull acc2[2][4] = {};
    for (int kt = 0; kt < K; kt += GBK) {
        {
            const int m = tid >> 2, kb = (tid & 3) * 4, gr = row0 + m;
            #pragma unroll
            for (int i = 0; i < 4; i++) {
                const int gk = kt + kb + i;
                float v = 0.0f;
                if (gk < K) v = (gk < K0) ? A0[(size_t)gr * K0 + gk] : A1[(size_t)gr * K1 + (gk - K0)];
                As[kb + i][m] = v;
            }
        }
        #pragma unroll
        for (int i = 0; i < 4; i++) {
            const int idx = tid + 256 * i, k = idx >> 6, n = idx & 63;
            const int gk = kt + k, gn = col0 + n;
            Wsm[k][n] = (gk < K && gn < N) ? W[(size_t)gk * ldw + gn] : 0.0f;
        }
        __syncthreads();
        #pragma unroll
        for (int k = 0; k < GBK; k++) {
            const ull a0 = *(const ull*)&As[k][ty * 4];
            const ull a1 = *(const ull*)&As[k][ty * 4 + 2];
            const float4 w4 = *(const float4*)&Wsm[k][tx * 4];
            ull wd[4] = {pack_dup(w4.x), pack_dup(w4.y), pack_dup(w4.z), pack_dup(w4.w)};
            #pragma unroll
            for (int j = 0; j < 4; j++) { fma2(acc2[0][j], a0, wd[j]); fma2(acc2[1][j], a1, wd[j]); }
        }
        __syncthreads();
    }
    #pragma unroll
    for (int i2 = 0; i2 < 2; i2++)
        #pragma unroll
        for (int j = 0; j < 4; j++) {
            float lo, hi; unpack2(acc2[i2][j], lo, hi);
            const int c = col0 + tx * 4 + j;
            if (c >= N) continue;
            float pair[2] = {lo, hi};
            #pragma unroll
            for (int u = 0; u < 2; u++) {
                const int r = row0 + ty * 4 + 2 * i2 + u;
                if (r >= M) continue;
                float v = pair[u];
                if (bias) v += bias[c];
                if (mode == 1) v = silu_f(v);
                C[(size_t)r * ldc + c] = v;
                if (outT) TILE_WR(outT, r, c, __float2bfloat16(v));
            }
        }
}

__global__ void timefeat_kernel(const float* __restrict__ t, float* __restrict__ feat)
{
    const int idx = blockIdx.x * blockDim.x + threadIdx.x;
    if (idx >= NODES * 128) return;
    const int node = idx >> 7, c = idx & 127, b = node >> 5;
    const float tv = t[b];
    const float kf = -logf(10000.0f) / 63.0f;
    float val = (c < 64) ? __sinf(tv * __expf((float)c * kf)) : __cosf(tv * __expf((float)(c - 64) * kf));
    feat[(size_t)node * 384 + 256 + c] = val;
}

__global__ void edgefeat_kernel(const float* __restrict__ frac, __nv_bfloat16* __restrict__ efT)
{
    const int idx = blockIdx.x * blockDim.x + threadIdx.x;
    if (idx >= NTILE * 128 * 64) return;
    const int tI = idx >> 13, rem = idx & 8191, r = rem >> 6, k = rem & 63;
    const int node = (tI << 2) + (r >> 5), j = r & 31, b = node >> 5;
    float val = 0.0f;
    if (k < 54) {
        const int a = (k < 27) ? k : (k - 27);
        const int dim = a / 9, f = a - dim * 9 + 1;
        float d = frac[(b * 32 + j) * 3 + dim] - frac[node * 3 + dim];
        d -= floorf(d);
        const float arg = d * (6.283185307179586f * (float)f);
        val = (k < 27) ? __sinf(arg) : __cosf(arg);
    }
    *(__nv_bfloat16*)((char*)efT + (size_t)tI * 16384 + sw128((uint32_t)(r * 128 + k * 2))) =
        __float2bfloat16(val);
}

__global__ void pack_w1t_kernel(const float* __restrict__ m1W, __nv_bfloat16* __restrict__ W1T)
{
    const int idx = blockIdx.x * blockDim.x + threadIdx.x;
    if (idx >= NLAY * 256 * 64) return;
    const int l = idx >> 14, rem = idx & 16383, n = rem >> 6, k = rem & 63;
    float v = 0.0f;
    if (k < 54) {
        const int a = (k < 27) ? k : (k - 27);
        const int dim = a / 9, f = a - dim * 9 + 1;
        const int row = 512 + ((k < 27) ? 0 : 30) + dim * 10 + f;
        v = m1W[(size_t)l * 578 * 256 + row * 256 + n];
    }
    *(__nv_bfloat16*)((char*)W1T + (size_t)l * 32768 + sw128((uint32_t)(n * 128 + k * 2))) =
        __float2bfloat16(v);
}

__global__ void pack_all_kernel(const float* __restrict__ m1W, const float* __restrict__ a1W,
                                const float* __restrict__ a2W, const float* __restrict__ m2W,
                                __nv_bfloat16* __restrict__ WB)
{
    const int idx = blockIdx.x * blockDim.x + threadIdx.x;
    if (idx >= 96 * 16384) return;
    const int chunk = idx >> 14, rem = idx & 16383, n = rem >> 6, kk = rem & 63;
    const int l = chunk / 24, cl = chunk - l * 24;
    const float* src; int k;
    if (cl < 4)       { src = m1W + (size_t)l * 578 * 256;         k = cl * 64 + kk; }
    else if (cl < 8)  { src = m1W + (size_t)l * 578 * 256 + 65536; k = (cl - 4) * 64 + kk; }
    else if (cl < 16) { src = a1W + (size_t)l * 512 * 256;         k = (cl - 8) * 64 + kk; }
    else if (cl < 20) { src = a2W + (size_t)l * 65536;             k = (cl - 16) * 64 + kk; }
    else              { src = m2W + (size_t)l * 65536;             k = (cl - 20) * 64 + kk; }
    *(__nv_bfloat16*)((char*)WB + (size_t)chunk * 32768 + sw128((uint32_t)(n * 128 + kk * 2)))
        = __float2bfloat16(src[(size_t)k * 256 + n]);
}

__global__ void prepq_kernel(const float* __restrict__ m1W, const float* __restrict__ m1b,
                             const float* __restrict__ lpolar, float* __restrict__ qb)
{
    const int l = blockIdx.x >> 7, gb = blockIdx.x & 127, c = threadIdx.x;
    const float* W1 = m1W + (size_t)l * 578 * 256;
    float q = m1b[l * 256 + c] + W1[542 * 256 + c] + W1[552 * 256 + c] + W1[562 * 256 + c];
    #pragma unroll
    for (int u = 0; u < 6; u++) q += lpolar[gb * 6 + u] * W1[(572 + u) * 256 + c];
    qb[((size_t)l * 128 + gb) * 256 + c] = q;
}

__global__ void layernorm_kernel(const float* __restrict__ x, const float* __restrict__ g,
                                 const float* __restrict__ b, float* __restrict__ yf)
{
    const int row = blockIdx.x, tid = threadIdx.x;
    const float v = x[(size_t)row * HID + tid];
    __shared__ float sr[8];
    float s = v;
    #pragma unroll
    for (int o = 16; o; o >>= 1) s += __shfl_xor_sync(~0u, s, o);
    if ((tid & 31) == 0) sr[tid >> 5] = s;
    __syncthreads();
    float tot = 0.0f;
    #pragma unroll
    for (int i = 0; i < 8; i++) tot += sr[i];
    const float mean = tot * (1.0f / 256.0f);
    const float d = v - mean;
    __syncthreads();
    float q = d * d;
    #pragma unroll
    for (int o = 16; o; o >>= 1) q += __shfl_xor_sync(~0u, q, o);
    if ((tid & 31) == 0) sr[tid >> 5] = q;
    __syncthreads();
    tot = 0.0f;
    #pragma unroll
    for (int i = 0; i < 8; i++) tot += sr[i];
    yf[(size_t)row * HID + tid] = d * rsqrtf(tot * (1.0f / 256.0f) + 1e-5f) * g[tid] + b[tid];
}

// ---------- fused LN + dual-P GEMM (layer 0 only; R12 bulk loads) ----------
#define TG_SMEM 197632
__global__ void __launch_bounds__(256, 1) lnp_tc(
    const float* __restrict__ nf, const float* __restrict__ g, const float* __restrict__ b,
    const __nv_bfloat16* __restrict__ Wp, const float* __restrict__ qb,
    float* __restrict__ PiQ, float* __restrict__ PjT)
{
    extern __shared__ char smraw[];
    const int tid = threadIdx.x, t = blockIdx.x;
#if HAS_TC
    char* sb = (char*)(((uintptr_t)smraw + 1023) & ~(uintptr_t)1023);
    float* stage = (float*)(sb + 65536);
    __shared__ uint32_t s_tmem[1];
    __shared__ __align__(8) unsigned long long s_bar[1];
    const int wid = tid >> 5, lid = tid & 31;
    const uint32_t bar = smu32(&s_bar[0]);
    if (tid == 0) mbar_init(bar, 1);
    if (wid == 0)
        asm volatile("tcgen05.alloc.cta_group::1.sync.aligned.shared::cta.b32 [%0], 512;"
                     :: "r"(smu32(s_tmem)) : "memory");
    __syncthreads();
    const uint32_t tb = s_tmem[0];

    {
        const float4* gsrc = (const float4*)(nf + (size_t)t * 128 * 256);
        for (int i = tid; i < 8192; i += 256) cp16(((float4*)stage) + i, gsrc + i);
    }
    cp_commit(); cp_wait<0>();
    __syncthreads();

    {
        const int r = tid >> 1, h = tid & 1;
        const float4* rowp = (const float4*)(stage + r * 256 + h * 128);
        float s = 0.f, s2 = 0.f;
        #pragma unroll
        for (int q = 0; q < 32; q++) {
            const float4 v = rowp[q];
            s  += v.x + v.y + v.z + v.w;
            s2 += v.x * v.x + v.y * v.y + v.z * v.z + v.w * v.w;
        }
        s  += __shfl_xor_sync(~0u, s, 1);
        s2 += __shfl_xor_sync(~0u, s2, 1);
        const float mean = s * (1.0f / 256.0f);
        const float rstd = rsqrtf(s2 * (1.0f / 256.0f) - mean * mean + 1e-5f);
        #pragma unroll
        for (int q = 0; q < 32; q++) {
            const float4 v = rowp[q];
            const int cb = h * 128 + q * 4;
            const float4 gg = *(const float4*)(g + cb);
            const float4 bb = *(const float4*)(b + cb);
            const float rv[4] = {
                (v.x - mean) * rstd * gg.x + bb.x, (v.y - mean) * rstd * gg.y + bb.y,
                (v.z - mean) * rstd * gg.z + bb.z, (v.w - mean) * rstd * gg.w + bb.w };
            #pragma unroll
            for (int e = 0; e < 4; e++) {
                const int c = cb + e;
                *(__nv_bfloat16*)(sb + (c >> 6) * 16384
                    + sw128((uint32_t)((r << 7) + ((c & 63) << 1)))) = __float2bfloat16(rv[e]);
            }
        }
    }
    __syncthreads();

    #pragma unroll 1
    for (int p = 0; p < 2; p++) {
        const float4* gw = (const float4*)(Wp + (size_t)p * 4 * 16384);
        for (int i = tid; i < 8192; i += 256) cp16((float4*)(sb + 65536) + i, gw + i);
        cp_commit(); cp_wait<0>();
        fence_pa();
        __syncthreads();
        if (tid == 0) {
            const uint32_t d = tb + (p ? 256u : 0u);
            #pragma unroll
            for (int q = 0; q < 4; q++) {
                const uint64_t ad = mk_desc(sb + q * 16384);
                const uint64_t bd = mk_desc(sb + 65536 + q * 32768);
                #pragma unroll
                for (int s = 0; s < 4; s++) mma_f16_ss(d, ad + 2 * s, bd + 2 * s, q > 0 || s > 0);
            }
            tc_commit(bar);
        }
        mbar_wait(bar, (uint32_t)p);
        tcf_a();
        __syncthreads();
    }

    const int half = wid >> 2, sp = wid & 3;
    const int node = t * 128 + sp * 32 + lid;
    const int gb = node >> 5, jn = node & 31;
    #pragma unroll 1
    for (int i = 0; i < 2; i++) {
        const int c0 = half * 128 + 64 * i;
        uint32_t r0[64], r1[64];
        TC_LD_X64(r0, tb + c0);
        TC_LD_X64(r1, tb + 256 + c0);
        tcw_ld();
        #pragma unroll
        for (int c = 0; c < 64; c++) {
            const int gc = c0 + c;
            PiQ[(size_t)node * 256 + gc] = __uint_as_float(r0[c]) + qb[(size_t)gb * 256 + gc];
            PjT[((size_t)gb * 256 + gc) * 32 + jn] = __uint_as_float(r1[c]);
        }
    }
    __syncthreads();
    if (wid == 0) {
        asm volatile("tcgen05.relinquish_alloc_permit.cta_group::1.sync.aligned;");
        asm volatile("tcgen05.dealloc.cta_group::1.sync.aligned.b32 %0, 512;" :: "r"(tb));
    }
#else
    float* Xs = (float*)smraw;
    for (int idx = tid; idx < 128; idx += 256) {
        const int node = t * 128 + idx;
        float s = 0.f, s2 = 0.f;
        for (int c = 0; c < 256; c++) { float v = nf[(size_t)node * 256 + c]; s += v; s2 += v * v; }
        const float mean = s / 256.f, rstd = rsqrtf(s2 / 256.f - mean * mean + 1e-5f);
        for (int c = 0; c < 256; c++)
            Xs[idx * 256 + c] = __bfloat162float(__float2bfloat16(
                (nf[(size_t)node * 256 + c] - mean) * rstd * g[c] + b[c]));
    }
    __syncthreads();
    for (int m = 0; m < 128; m++) {
        const int node = t * 128 + m, c = tid, gb = node >> 5, jn = node & 31;
        float a0 = 0.f, a1v = 0.f;
        for (int k = 0; k < 256; k++) {
            const float a = Xs[m * 256 + k];
            const uint32_t off = sw128((uint32_t)(c * 128 + (k & 63) * 2));
            a0  += a * __bfloat162float(*(const __nv_bfloat16*)((const char*)Wp + (size_t)(k >> 6) * 32768 + off));
            a1v += a * __bfloat162float(*(const __nv_bfloat16*)((const char*)Wp + (size_t)(4 + (k >> 6)) * 32768 + off));
        }
        PiQ[(size_t)node * 256 + c] = a0 + qb[(size_t)gb * 256 + c];
        PjT[((size_t)gb * 256 + c) * 32 + jn] = a1v;
    }
#endif
}

// ---------- fused node update (R12 bulk loads) ----------
__global__ void __launch_bounds__(256, 1) fused_node(
    const __nv_bfloat16* __restrict__ A0, const __nv_bfloat16* __restrict__ A1,
    const __nv_bfloat16* __restrict__ W1, const __nv_bfloat16* __restrict__ W2,
    const float* __restrict__ b1, const float* __restrict__ b2,
    float* __restrict__ nf, __nv_bfloat16* __restrict__ nfT,
    int doP, const float* __restrict__ g, const float* __restrict__ b,
    const __nv_bfloat16* __restrict__ Wp, const float* __restrict__ qbn,
    float* __restrict__ PiQ, float* __restrict__ PjT)
{
    extern __shared__ char smraw[];
    const int tid = threadIdx.x, t = blockIdx.x;
#if HAS_TC
    char* sb = (char*)(((uintptr_t)smraw + 1023) & ~(uintptr_t)1023);
    float* stage = (float*)(sb + 65536);
    __shared__ uint32_t s_tmem[1];
    __shared__ __align__(8) unsigned long long s_bar[1];
    const int wid = tid >> 5, lid = tid & 31;
    const uint32_t bar = smu32(&s_bar[0]);
    if (tid == 0) mbar_init(bar, 1);
    if (wid == 0)
        asm volatile("tcgen05.alloc.cta_group::1.sync.aligned.shared::cta.b32 [%0], 512;"
                     :: "r"(smu32(s_tmem)) : "memory");
    __syncthreads();
    const uint32_t tb = s_tmem[0];

    #pragma unroll 1
    for (int p = 0; p < 2; p++) {
        const __nv_bfloat16* Ac = p ? A1 : A0;
        const float4* ga = (const float4*)(Ac + (size_t)t * 4 * 8192);
        for (int i = tid; i < 4096; i += 256) cp16((float4*)sb + i, ga + i);
        const float4* gw = (const float4*)(W1 + (size_t)p * 4 * 16384);
        for (int i = tid; i < 8192; i += 256) cp16((float4*)(sb + 65536) + i, gw + i);
        cp_commit(); cp_wait<0>();
        fence_pa();
        __syncthreads();
        if (tid == 0) {
            #pragma unroll
            for (int q = 0; q < 4; q++) {
                const uint64_t ad = mk_desc(sb + q * 16384);
                const uint64_t bd = mk_desc(sb + 65536 + q * 32768);
                #pragma unroll
                for (int s = 0; s < 4; s++)
                    mma_f16_ss(tb, ad + 2 * s, bd + 2 * s, p > 0 || q > 0 || s > 0);
            }
            tc_commit(bar);
        }
        mbar_wait(bar, (uint32_t)p);
        tcf_a();
        __syncthreads();
    }

    {
        const float4* gw = (const float4*)W2;
        for (int i = tid; i < 8192; i += 256) cp16((float4*)(sb + 65536) + i, gw + i);
        cp_commit();
    }

    const int half = wid >> 2, sp = wid & 3;
    const int node = t * 128 + sp * 32 + lid;
    const int m = sp * 32 + lid;

    #pragma unroll 1
    for (int i = 0; i < 2; i++) {
        const int c0 = half * 128 + 64 * i;
        uint32_t r[64];
        TC_LD_X64(r, tb + c0);
        float bb[64];
        #pragma unroll
        for (int u = 0; u < 16; u++) *(float4*)&bb[4 * u] = ((const float4*)(b1 + c0))[u];
        tcw_ld();
        float v[64];
        #pragma unroll
        for (int c = 0; c < 64; c++) v[c] = silu_t(__uint_as_float(r[c]) + bb[c]);
        uint32_t xp[32];
        #pragma unroll
        for (int p = 0; p < 32; p++)
            asm("cvt.rn.bf16x2.f32 %0, %1, %2;" : "=r"(xp[p]) : "f"(v[2 * p + 1]), "f"(v[2 * p]));
        TC_ST_X32(tb + 256 + half * 64 + 32 * i + ((uint32_t)sp << 21), xp);
    }
    tcw_st();
    tcf_b();
    cp_wait<0>();
    fence_pa();
    __syncthreads();

    if (tid == 0) {
        tcf_a();
        const uint64_t bd = mk_desc(sb + 65536);
        #pragma unroll
        for (int s = 0; s < 16; s++)
            mma_f16_ts(tb, tb + 256 + 8 * s, bd + (uint64_t)((s >> 2) * 2048 + (s & 3) * 2), s > 0);
        tc_commit(bar);
    }
    mbar_wait(bar, 0u);
    tcf_a();

    #pragma unroll 1
    for (int i = 0; i < 2; i++) {
        const int c0 = half * 128 + 64 * i;
        uint32_t r[64];
        TC_LD_X64(r, tb + c0);
        float bb[64];
        #pragma unroll
        for (int u = 0; u < 16; u++) *(float4*)&bb[4 * u] = ((const float4*)(b2 + c0))[u];
        tcw_ld();
        #pragma unroll
        for (int c = 0; c < 64; c++) {
            const int gc = c0 + c;
            const float nv = nf[(size_t)node * 256 + gc] + silu_t(__uint_as_float(r[c]) + bb[c]);
            nf[(size_t)node * 256 + gc] = nv;
            TILE_WR(nfT, node, gc, __float2bfloat16(nv));
            if (doP) stage[m * 256 + gc] = nv;
        }
    }
    tcf_b();
    __syncthreads();

    if (doP) {
        {
            const int r = tid >> 1, h = tid & 1;
            const float4* rowp = (const float4*)(stage + r * 256 + h * 128);
            float s = 0.f, s2 = 0.f;
            #pragma unroll
            for (int q = 0; q < 32; q++) {
                const float4 v = rowp[q];
                s  += v.x + v.y + v.z + v.w;
                s2 += v.x * v.x + v.y * v.y + v.z * v.z + v.w * v.w;
            }
            s  += __shfl_xor_sync(~0u, s, 1);
            s2 += __shfl_xor_sync(~0u, s2, 1);
            const float mean = s * (1.0f / 256.0f);
            const float rstd = rsqrtf(s2 * (1.0f / 256.0f) - mean * mean + 1e-5f);
            #pragma unroll
            for (int q = 0; q < 32; q++) {
                const float4 v = rowp[q];
                const int cb = h * 128 + q * 4;
                const float4 gg = *(const float4*)(g + cb);
                const float4 bbv = *(const float4*)(b + cb);
                const float rv[4] = {
                    (v.x - mean) * rstd * gg.x + bbv.x, (v.y - mean) * rstd * gg.y + bbv.y,
                    (v.z - mean) * rstd * gg.z + bbv.z, (v.w - mean) * rstd * gg.w + bbv.w };
                #pragma unroll
                for (int e = 0; e < 4; e++) {
                    const int c = cb + e;
                    *(__nv_bfloat16*)(sb + (c >> 6) * 16384
                        + sw128((uint32_t)((r << 7) + ((c & 63) << 1)))) = __float2bfloat16(rv[e]);
                }
            }
        }
        __syncthreads();

        #pragma unroll 1
        for (int p = 0; p < 2; p++) {
            const float4* gw = (const float4*)(Wp + (size_t)p * 4 * 16384);
            for (int i = tid; i < 8192; i += 256) cp16((float4*)(sb + 65536) + i, gw + i);
            cp_commit(); cp_wait<0>();
            fence_pa();
            __syncthreads();
            if (tid == 0) {
                tcf_a();
                const uint32_t d = tb + (p ? 256u : 0u);
                #pragma unroll
                for (int q = 0; q < 4; q++) {
                    const uint64_t ad = mk_desc(sb + q * 16384);
                    const uint64_t bd = mk_desc(sb + 65536 + q * 32768);
                    #pragma unroll
                    for (int s = 0; s < 4; s++) mma_f16_ss(d, ad + 2 * s, bd + 2 * s, q > 0 || s > 0);
                }
                tc_commit(bar);
            }
            mbar_wait(bar, (uint32_t)(p ? 0 : 1));
            tcf_a();
            __syncthreads();
        }

        const int gb = node >> 5, jn = node & 31;
        #pragma unroll 1
        for (int i = 0; i < 2; i++) {
            const int c0 = half * 128 + 64 * i;
            uint32_t r0[64], r1[64];
            TC_LD_X64(r0, tb + c0);
            TC_LD_X64(r1, tb + 256 + c0);
            tcw_ld();
            #pragma unroll
            for (int c = 0; c < 64; c++) {
                const int gc = c0 + c;
                PiQ[(size_t)node * 256 + gc] = __uint_as_float(r0[c]) + qbn[(size_t)gb * 256 + gc];
                PjT[((size_t)gb * 256 + gc) * 32 + jn] = __uint_as_float(r1[c]);
            }
        }
    }
    __syncthreads();
    if (wid == 0) {
        asm volatile("tcgen05.relinquish_alloc_permit.cta_group::1.sync.aligned;");
        asm volatile("tcgen05.dealloc.cta_group::1.sync.aligned.b32 %0, 512;" :: "r"(tb));
    }
#else
    float* Xs = (float*)smraw;
    for (int m2 = 0; m2 < 128; m2++) {
        const int node = t * 128 + m2, c = tid;
        float acc = b1[c];
        for (int k = 0; k < 512; k++) {
            const __nv_bfloat16* At = (k < 256) ? A0 : A1;
            const int kk = k & 255;
            float a = __bfloat162float(*(const __nv_bfloat16*)((const char*)At
                        + (size_t)((t << 2) + (kk >> 6)) * 16384
                        + sw128((uint32_t)((m2 << 7) + ((kk & 63) << 1)))));
            float w = __bfloat162float(*(const __nv_bfloat16*)((const char*)W1
                        + (size_t)(k >> 6) * 32768 + sw128((uint32_t)(c * 128 + (k & 63) * 2))));
            acc += a * w;
        }
        Xs[m2 * 256 + c] = __bfloat162float(__float2bfloat16(silu_f(acc)));
        __syncthreads();
    }
    for (int m2 = 0; m2 < 128; m2++) {
        const int node = t * 128 + m2, c = tid;
        float acc = b2[c];
        for (int k = 0; k < 256; k++)
            acc += Xs[m2 * 256 + k] * __bfloat162float(*(const __nv_bfloat16*)((const char*)W2
                    + (size_t)(k >> 6) * 32768 + sw128((uint32_t)(c * 128 + (k & 63) * 2))));
        const float nv = nf[(size_t)node * 256 + c] + silu_f(acc);
        nf[(size_t)node * 256 + c] = nv;
        TILE_WR(nfT, node, c, __float2bfloat16(nv));
    }
    __syncthreads();
    if (doP) {
        for (int m2 = 0; m2 < 128; m2++) {
            const int node = t * 128 + m2;
            if (tid == 0) {
                float s = 0.f, s2 = 0.f;
                for (int c = 0; c < 256; c++) { float v = nf[(size_t)node * 256 + c]; s += v; s2 += v * v; }
                Xs[m2 * 256] = s / 256.f;
                Xs[m2 * 256 + 1] = rsqrtf(s2 / 256.f - (s / 256.f) * (s / 256.f) + 1e-5f);
            }
            __syncthreads();
            const float mean = Xs[m2 * 256], rstd = Xs[m2 * 256 + 1];
            const float hv = __bfloat162float(__float2bfloat16(
                (nf[(size_t)node * 256 + tid] - mean) * rstd * g[tid] + b[tid]));
            __syncthreads();
            Xs[m2 * 256 + tid] = hv;
            __syncthreads();
        }
        for (int m2 = 0; m2 < 128; m2++) {
            const int node = t * 128 + m2, c = tid, gb = node >> 5, jn = node & 31;
            float a0 = 0.f, a1v = 0.f;
            for (int k = 0; k < 256; k++) {
                const float a = Xs[m2 * 256 + k];
                const uint32_t off = sw128((uint32_t)(c * 128 + (k & 63) * 2));
                a0  += a * __bfloat162float(*(const __nv_bfloat16*)((const char*)Wp + (size_t)(k >> 6) * 32768 + off));
                a1v += a * __bfloat162float(*(const __nv_bfloat16*)((const char*)Wp + (size_t)(4 + (k >> 6)) * 32768 + off));
            }
            PiQ[(size_t)node * 256 + c] = a0 + qbn[(size_t)gb * 256 + c];
            PjT[((size_t)gb * 256 + c) * 32 + jn] = a1v;
        }
    }
#endif
}

// ---------- fused edge kernel (MMA2 split into two N=128 halves, overlapped epilogue) ----------
#define EDGE_SMEM_REQ 230400
__global__ void __launch_bounds__(256, 1) edge_msg_tc(
    const float* __restrict__ PiQ, const float* __restrict__ PjT,
    const __nv_bfloat16* __restrict__ efT, const __nv_bfloat16* __restrict__ W1T,
    const __nv_bfloat16* __restrict__ W2T, const float* __restrict__ b2,
    __nv_bfloat16* __restrict__ msgT)
{
    extern __shared__ char smraw[];
#if HAS_TC
    char* sb = (char*)(((uintptr_t)smraw + 1023) & ~(uintptr_t)1023);
    float* Pjs = (float*)(sb + 65536);
    __shared__ uint32_t s_tmem[1];
    __shared__ __align__(8) unsigned long long s_bar[3];

    const int tid = threadIdx.x, wid = tid >> 5, lid = tid & 31;
    const int gb = blockIdx.x;
    const uint32_t barE  = smu32(&s_bar[0]);
    const uint32_t barYA = smu32(&s_bar[1]);
    const uint32_t barYB = smu32(&s_bar[2]);

    if (tid == 0) { mbar_init(barE, 1); mbar_init(barYA, 1); mbar_init(barYB, 1); }
    if (wid == 0)
        asm volatile("tcgen05.alloc.cta_group::1.sync.aligned.shared::cta.b32 [%0], 512;"
                     :: "r"(smu32(s_tmem)) : "memory");
    __syncthreads();
    const uint32_t tb = s_tmem[0];

    {   // G1: ef tile0
        const float4* g = (const float4*)efT + (size_t)gb * 8192;
        for (int i = tid; i < 1024; i += 256) cp16((float4*)sb + i, g + i);
    }
    cp_commit();
    {   // G2: W1 + Pjs + W2
        const float4* g1 = (const float4*)W1T;
        for (int i = tid; i < 2048; i += 256) cp16((float4*)(sb + 32768) + i, g1 + i);
        const float4* gp = (const float4*)(PjT + (size_t)gb * 8192);
        for (int i = tid; i < 2048; i += 256) cp16((float4*)(sb + 65536) + i, gp + i);
        const float4* g2 = (const float4*)W2T;
        for (int i = tid; i < 8192; i += 256) cp16((float4*)(sb + 98304) + i, g2 + i);
    }
    cp_commit();
    {   // G3: ef tile1
        const float4* g = (const float4*)efT + (size_t)gb * 8192 + 1024;
        for (int i = tid; i < 1024; i += 256) cp16((float4*)(sb + 16384) + i, g + i);
    }
    cp_commit();

    const uint64_t w1d = mk_desc(sb + 32768);
    const uint64_t w2d = mk_desc(sb + 98304);
    const int half = wid >> 2, nodeL = wid & 3;

    #pragma unroll 1
    for (int t = 0; t < 8; t++) {
        char* efb = sb + (t & 1) * 16384;
        const int node = gb * 32 + 4 * t + nodeL;
        const uint32_t ph = (uint32_t)(t & 1);

        cp_wait<1>();
        fence_pa();
        __syncthreads();
        // MMA1: N=256 in one commit (unchanged)
        if (tid == 0) {
            const uint64_t ad = mk_desc(efb);
            #pragma unroll
            for (int s = 0; s < 4; s++) mma_f16_ss(tb, ad + 2 * s, w1d + 2 * s, s > 0);
            tc_commit(barE);
        }
        mbar_wait(barE, ph);
        tcf_a();
        if (t < 6) {
            const float4* g = (const float4*)efT + (size_t)(gb * 8 + t + 2) * 1024;
            for (int i = tid; i < 1024; i += 256) cp16((float4*)efb + i, g + i);
        }
        cp_commit();

        // phase1: X = silu(E + PiQ + Pj)
        const float* piqp = PiQ + (size_t)node * 256;
        #pragma unroll 1
        for (int i = 0; i < 2; i++) {
            const int c0 = half * 128 + 64 * i;
            uint32_t r[64];
            TC_LD_X64(r, tb + c0);
            float piq[64];
            #pragma unroll
            for (int u = 0; u < 16; u++) *(float4*)&piq[4 * u] = ((const float4*)(piqp + c0))[u];
            tcw_ld();
            float v[64];
            #pragma unroll
            for (int c = 0; c < 64; c++)
                v[c] = silu_t(__uint_as_float(r[c]) + piq[c] + Pjs[(c0 + c) * 32 + lid]);
            uint32_t xp[32];
            #pragma unroll
            for (int p = 0; p < 32; p++)
                asm("cvt.rn.bf16x2.f32 %0, %1, %2;" : "=r"(xp[p]) : "f"(v[2 * p + 1]), "f"(v[2 * p]));
            TC_ST_X32(tb + 384 + half * 64 + 32 * i + ((uint32_t)nodeL << 21), xp);
        }
        tcw_st();
        tcf_b();
        __syncthreads();

        // MMA2 split into two N=128 halves; epilogue-a overlaps MMA2-b
        if (tid == 0) {
            tcf_a();
            #pragma unroll
            for (int s = 0; s < 16; s++)
                mma_f16_ts_n(tb, tb + 384 + 8 * s,
                             w2d + (uint64_t)((s >> 2) * 2048 + (s & 3) * 2),
                             IDESC_BF16_N128, s > 0);
            tc_commit(barYA);
            #pragma unroll
            for (int s = 0; s < 16; s++)
                mma_f16_ts_n(tb + 128, tb + 384 + 8 * s,
                             w2d + 1024 + (uint64_t)((s >> 2) * 2048 + (s & 3) * 2),
                             IDESC_BF16_N128, s > 0);
            tc_commit(barYB);
        }
        mbar_wait(half == 0 ? barYA : barYB, ph);
        tcf_a();

        // epilogue on own half (cols half*128 .. half*128+127)
        #pragma unroll 1
        for (int i = 0; i < 2; i++) {
            const int c0 = half * 128 + 64 * i;
            uint32_t r[64];
            TC_LD_X64(r, tb + c0);
            float bb[64];
            #pragma unroll
            for (int u = 0; u < 16; u++) *(float4*)&bb[4 * u] = ((const float4*)(b2 + c0))[u];
            tcw_ld();
            float v[64];
            #pragma unroll
            for (int c = 0; c < 64; c++) v[c] = silu_t(__uint_as_float(r[c]) + bb[c]);
            #pragma unroll
            for (int off = 16; off; off >>= 1) {
                const bool hi = (lid & off) != 0;
                #pragma unroll
                for (int k = 0; k < off; k++) {
                    float s0 = hi ? v[k] : v[k + off];
                    float rc0 = __shfl_xor_sync(~0u, s0, off);
                    float k0 = hi ? v[k + off] : v[k];
                    v[k] = k0 + rc0;
                    float s1 = hi ? v[32 + k] : v[32 + k + off];
                    float rc1 = __shfl_xor_sync(~0u, s1, off);
                    float k1 = hi ? v[32 + k + off] : v[32 + k];
                    v[32 + k] = k1 + rc1;
                }
            }
            TILE_WR(msgT, node, c0 + lid, __float2bfloat16(v[0] * 0.03125f));
            TILE_WR(msgT, node, c0 + 32 + lid, __float2bfloat16(v[32] * 0.03125f));
        }
        __syncthreads();   // warps 4-7 passed only after MMA2-b done -> X/D overwrite safe
    }

    if (wid == 0) {
        asm volatile("tcgen05.relinquish_alloc_permit.cta_group::1.sync.aligned;");
        asm volatile("tcgen05.dealloc.cta_group::1.sync.aligned.b32 %0, 512;" :: "r"(tb));
    }
#else
    float* Xf = (float*)smraw;
    const int tid = threadIdx.x, gb = blockIdx.x;
    for (int nl = 0; nl < 32; nl++) {
        const int node = gb * 32 + nl;
        const int tI = node >> 2, rb = (node & 3) * 32;
        for (int idx = tid; idx < 32 * 256; idx += 256) {
            const int j = idx >> 8, c = idx & 255;
            const int r = rb + j;
            float e = 0.f;
            for (int k = 0; k < 54; k++) {
                float a = __bfloat162float(*(const __nv_bfloat16*)((const char*)efT
                            + (size_t)tI * 16384 + sw128((uint32_t)(r * 128 + k * 2))));
                float w = __bfloat162float(*(const __nv_bfloat16*)((const char*)W1T
                            + sw128((uint32_t)(c * 128 + k * 2))));
                e += a * w;
            }
            e += PiQ[(size_t)node * 256 + c] + PjT[((size_t)(gb * 256 + c)) * 32 + j];
            Xf[j * 260 + c] = silu_f(e);
        }
        __syncthreads();
        const int c = tid;
        float acc = 0.f;
        for (int j = 0; j < 32; j++) {
            float y = b2[c];
            for (int k = 0; k < 256; k++) {
                const size_t byte = (size_t)(k >> 6) * 32768 + (c >> 3) * 1024
                                  + sw128((uint32_t)((c & 7) * 128 + (k & 63) * 2));
                y += Xf[j * 260 + k] * __bfloat162float(*(const __nv_bfloat16*)((const char*)W2T + byte));
            }
            acc += silu_f(y);
        }
        TILE_WR(msgT, node, c, __float2bfloat16(acc * (1.0f / 32.0f)));
        __syncthreads();
    }
#endif
}

__global__ void graphmean_kernel(const float* __restrict__ h, float* __restrict__ gf)
{
    const int b = blockIdx.x, c = threadIdx.x;
    float s = 0.0f;
    #pragma unroll
    for (int i = 0; i < 32; i++) s += h[(size_t)((b << 5) + i) * HID + c];
    gf[(size_t)b * HID + c] = s * (1.0f / 32.0f);
}

static void run_gemm(cudaStream_t s, const float* A0, int K0, const float* A1, int K1,
                     const float* W, int ldw, const float* bias,
                     float* C, int ldc, int M, int N, int mode,
                     __nv_bfloat16* outT = nullptr)
{
    dim3 grid((M + GBM - 1) / GBM, (N + GBN - 1) / GBN);
    gemm_kernel<<<grid, 256, 0, s>>>(A0, K0, A1, K1, W, ldw, bias, C, ldc, M, N, mode, outT);
}

extern "C" void kernel_launch(void* const* d_in, const int* in_sizes, int n_in,
                              void* d_out, int out_size)
{
    const float* t          = (const float*)d_in[0];
    const float* atom_types = (const float*)d_in[1];
    const float* frac       = (const float*)d_in[2];
    const float* l_polar    = (const float*)d_in[3];
    const float* Ws      = (const float*)d_in[5];
    const float* bs      = (const float*)d_in[6];
    const float* Wn      = (const float*)d_in[7];
    const float* bn      = (const float*)d_in[8];
    const float* ln_g    = (const float*)d_in[9];
    const float* ln_b    = (const float*)d_in[10];
    const float* m1_W    = (const float*)d_in[11];
    const float* m1_b    = (const float*)d_in[12];
    const float* m2_W    = (const float*)d_in[13];
    const float* m2_b    = (const float*)d_in[14];
    const float* a1_W    = (const float*)d_in[15];
    const float* a1_b    = (const float*)d_in[16];
    const float* a2_W    = (const float*)d_in[17];
    const float* a2_b    = (const float*)d_in[18];
    const float* fln_g   = (const float*)d_in[19];
    const float* fln_b   = (const float*)d_in[20];
    const float* type_W  = (const float*)d_in[21];
    const float* type_b  = (const float*)d_in[22];
    const float* polar_W = (const float*)d_in[23];
    const float* frac_W  = (const float*)d_in[24];
    float* out = (float*)d_out;

    float *feat, *nf, *h, *PiQ, *PjT, *gf, *qb;
    __nv_bfloat16 *efT, *W1T, *WB, *nfT, *msgT;
    cudaGetSymbolAddress((void**)&feat, g_feat);
    cudaGetSymbolAddress((void**)&nf,   g_nf);
    cudaGetSymbolAddress((void**)&h,    g_h);
    cudaGetSymbolAddress((void**)&PiQ,  g_PiQ);
    cudaGetSymbolAddress((void**)&PjT,  g_PjT);
    cudaGetSymbolAddress((void**)&gf,   g_gf);
    cudaGetSymbolAddress((void**)&qb,   g_qb);
    cudaGetSymbolAddress((void**)&efT,  g_efT);
    cudaGetSymbolAddress((void**)&W1T,  g_W1T);
    cudaGetSymbolAddress((void**)&WB,   g_WB);
    cudaGetSymbolAddress((void**)&nfT,  g_nfT);
    cudaGetSymbolAddress((void**)&msgT, g_msgT);

    cudaFuncSetAttribute(edge_msg_tc, cudaFuncAttributeMaxDynamicSharedMemorySize, EDGE_SMEM_REQ);
    cudaFuncSetAttribute(lnp_tc, cudaFuncAttributeMaxDynamicSharedMemorySize, TG_SMEM);
    cudaFuncSetAttribute(fused_node, cudaFuncAttributeMaxDynamicSharedMemorySize, TG_SMEM);

    static cudaStream_t s2 = nullptr;
    static cudaEvent_t ev0, ev1, ev2, ev3;
    if (!s2) {
        cudaStreamCreateWithFlags(&s2, cudaStreamNonBlocking);
        cudaEventCreateWithFlags(&ev0, cudaEventDisableTiming);
        cudaEventCreateWithFlags(&ev1, cudaEventDisableTiming);
        cudaEventCreateWithFlags(&ev2, cudaEventDisableTiming);
        cudaEventCreateWithFlags(&ev3, cudaEventDisableTiming);
    }
    cudaStream_t s = 0;

    // fork: branch B (edge features + weight packs) on s2, branch A (node features) on s
    cudaEventRecord(ev0, s);
    cudaStreamWaitEvent(s2, ev0, 0);
    edgefeat_kernel<<<(NTILE * 128 * 64) / 256, 256, 0, s2>>>(frac, efT);
    pack_w1t_kernel<<<(NLAY * 256 * 64) / 256, 256, 0, s2>>>(m1_W, W1T);
    pack_all_kernel<<<(96 * 16384) / 256, 256, 0, s2>>>(m1_W, a1_W, a2_W, m2_W, WB);
    prepq_kernel<<<NLAY * BGR, 256, 0, s2>>>(m1_W, m1_b, l_polar, qb);
    cudaEventRecord(ev1, s2);

    timefeat_kernel<<<(NODES * 128 + 255) / 256, 256, 0, s>>>(t, feat);
    run_gemm(s, atom_types, TYPED, nullptr, 0, Ws, HID, bs, feat, 384, NODES, HID, 0);
    run_gemm(s, feat, 384, nullptr, 0, Wn, HID, bn, nf, HID, NODES, HID, 0, nfT);
    cudaStreamWaitEvent(s, ev1, 0);

    lnp_tc<<<32, 256, TG_SMEM, s>>>(nf, ln_g, ln_b, WB, qb, PiQ, PjT);

    for (int l = 0; l < NLAY; l++) {
        __nv_bfloat16* WL = WB + (size_t)l * 24 * 16384;
        edge_msg_tc<<<BGR, 256, EDGE_SMEM_REQ, s>>>(
            PiQ, PjT, efT, W1T + (size_t)l * 16384, WL + 20 * 16384, m2_b + l * HID, msgT);
        const int doP = (l < NLAY - 1) ? 1 : 0;
        const int ln = doP ? (l + 1) : 0;
        fused_node<<<32, 256, TG_SMEM, s>>>(
            nfT, msgT, WL + 8 * 16384, WL + 16 * 16384,
            a1_b + l * HID, a2_b + l * HID, nf, nfT,
            doP, ln_g + ln * HID, ln_b + ln * HID,
            WB + (size_t)ln * 24 * 16384, qb + (size_t)ln * BGR * HID, PiQ, PjT);
    }

    layernorm_kernel<<<NODES, 256, 0, s>>>(nf, fln_g, fln_b, h);

    // fork readouts: frac gemm on s2, rest on s
    cudaEventRecord(ev2, s);
    cudaStreamWaitEvent(s2, ev2, 0);
    run_gemm(s2, h, HID, nullptr, 0, frac_W, 3, nullptr,
             out + (size_t)NODES * TYPED + (size_t)BGR * 6, 3, NODES, 3, 0);
    cudaEventRecord(ev3, s2);

    graphmean_kernel<<<BGR, 256, 0, s>>>(h, gf);
    run_gemm(s, gf, HID, nullptr, 0, polar_W, 6, nullptr, out + (size_t)NODES * TYPED, 6, BGR, 6, 0);
    run_gemm(s, h, HID, nullptr, 0, type_W, TYPED, type_b, out, TYPED, NODES, TYPED, 0);
    cudaStreamWaitEvent(s, ev3, 0);
}

// round 15
// speedup vs baseline: 1.0252x; 1.0252x over previous
#include <cuda_runtime.h>
#include <cuda_bf16.h>
#include <math.h>
#include <stdint.h>

#define BGR   128
#define NODES 4096
#define HID   256
#define TYPED 100
#define NLAY  4
#define NTILE 1024

#if defined(__CUDA_ARCH_FEAT_SM103_ALL) || defined(__CUDA_ARCH_FEAT_SM100_ALL) || defined(__CUDA_ARCH_SPECIFIC__) || defined(__CUDA_ARCH_FAMILY_SPECIFIC__)
#define HAS_TC 1
#else
#define HAS_TC 0
#endif

__device__ float g_feat[NODES * 384];
__device__ float g_nf  [NODES * HID];
__device__ float g_h   [NODES * HID];
__device__ float g_PiQ [NODES * HID];
__device__ float g_PjT [BGR * HID * 32];
__device__ float g_gf  [BGR * HID];
__device__ float g_qb  [NLAY * BGR * HID];
__device__ __nv_bfloat16 g_efT [(size_t)NTILE * 128 * 64];
__device__ __nv_bfloat16 g_W1T [NLAY * 256 * 64];
__device__ __nv_bfloat16 g_WB  [96 * 16384];
__device__ __nv_bfloat16 g_nfT [NODES * HID];
__device__ __nv_bfloat16 g_msgT[NODES * HID];

typedef unsigned long long ull;

__device__ __forceinline__ float silu_f(float x) { return x / (1.0f + __expf(-x)); }
__device__ __forceinline__ float silu_t(float x) {
    float xh = 0.5f * x, t;
    asm("tanh.approx.f32 %0, %1;" : "=f"(t) : "f"(xh));
    return fmaf(xh, t, xh);
}
__device__ __forceinline__ ull pack_dup(float f) { ull r; asm("mov.b64 %0, {%1,%1};" : "=l"(r) : "f"(f)); return r; }
__device__ __forceinline__ void unpack2(ull v, float& lo, float& hi) { asm("mov.b64 {%0,%1}, %2;" : "=f"(lo), "=f"(hi) : "l"(v)); }
__device__ __forceinline__ void fma2(ull& a, ull x, ull y) { asm("fma.rn.f32x2 %0, %1, %2, %0;" : "+l"(a) : "l"(x), "l"(y)); }
__device__ __forceinline__ void cp16(void* sdst, const void* gsrc) {
    unsigned s = (unsigned)__cvta_generic_to_shared(sdst);
    asm volatile("cp.async.cg.shared.global [%0], [%1], 16;" :: "r"(s), "l"(gsrc));
}
__device__ __forceinline__ void cp_commit() { asm volatile("cp.async.commit_group;"); }
template<int N> __device__ __forceinline__ void cp_wait() { asm volatile("cp.async.wait_group %0;" :: "n"(N)); }
__device__ __forceinline__ uint32_t smu32(const void* p) { return (uint32_t)__cvta_generic_to_shared(p); }
__device__ __forceinline__ void mbar_init(uint32_t a, uint32_t c) {
    asm volatile("mbarrier.init.shared.b64 [%0], %1;" :: "r"(a), "r"(c) : "memory");
}
__device__ __forceinline__ void mbar_wait(uint32_t a, uint32_t ph) {
    asm volatile("{\n\t.reg .pred P;\nWL%=:\n\t"
        "mbarrier.try_wait.parity.acquire.cta.shared::cta.b64 P, [%0], %1, 0x989680;\n\t"
        "@!P bra WL%=;\n\t}" :: "r"(a), "r"(ph) : "memory");
}
__device__ __forceinline__ void fence_pa() { asm volatile("fence.proxy.async.shared::cta;" ::: "memory"); }
__device__ __forceinline__ uint32_t sw128(uint32_t b) { return b ^ ((b >> 3) & 0x70); }

#define TILE_WR(base, node, c, val) \
    *(__nv_bfloat16*)((char*)(base) + (size_t)((((node) >> 7) << 2) + ((c) >> 6)) * 16384 \
        + sw128((uint32_t)((((node) & 127) << 7) + (((c) & 63) << 1)))) = (val)

#if HAS_TC
__device__ __forceinline__ void tcf_b() { asm volatile("tcgen05.fence::before_thread_sync;" ::: "memory"); }
__device__ __forceinline__ void tcf_a() { asm volatile("tcgen05.fence::after_thread_sync;" ::: "memory"); }
__device__ __forceinline__ void tcw_ld() { asm volatile("tcgen05.wait::ld.sync.aligned;" ::: "memory"); }
__device__ __forceinline__ void tcw_st() { asm volatile("tcgen05.wait::st.sync.aligned;" ::: "memory"); }
__device__ __forceinline__ void tc_commit(uint32_t b) {
    asm volatile("tcgen05.commit.cta_group::1.mbarrier::arrive::one.shared::cluster.b64 [%0];" :: "r"(b) : "memory");
}
#define TC_LD_X64(r, a) \
    asm volatile("tcgen05.ld.sync.aligned.32x32b.x64.b32 " \
        "{%0,%1,%2,%3,%4,%5,%6,%7,%8,%9,%10,%11,%12,%13,%14,%15," \
        "%16,%17,%18,%19,%20,%21,%22,%23,%24,%25,%26,%27,%28,%29,%30,%31," \
        "%32,%33,%34,%35,%36,%37,%38,%39,%40,%41,%42,%43,%44,%45,%46,%47," \
        "%48,%49,%50,%51,%52,%53,%54,%55,%56,%57,%58,%59,%60,%61,%62,%63}, [%64];" \
        : "=r"((r)[0]),"=r"((r)[1]),"=r"((r)[2]),"=r"((r)[3]),"=r"((r)[4]),"=r"((r)[5]),"=r"((r)[6]),"=r"((r)[7]), \
          "=r"((r)[8]),"=r"((r)[9]),"=r"((r)[10]),"=r"((r)[11]),"=r"((r)[12]),"=r"((r)[13]),"=r"((r)[14]),"=r"((r)[15]), \
          "=r"((r)[16]),"=r"((r)[17]),"=r"((r)[18]),"=r"((r)[19]),"=r"((r)[20]),"=r"((r)[21]),"=r"((r)[22]),"=r"((r)[23]), \
          "=r"((r)[24]),"=r"((r)[25]),"=r"((r)[26]),"=r"((r)[27]),"=r"((r)[28]),"=r"((r)[29]),"=r"((r)[30]),"=r"((r)[31]), \
          "=r"((r)[32]),"=r"((r)[33]),"=r"((r)[34]),"=r"((r)[35]),"=r"((r)[36]),"=r"((r)[37]),"=r"((r)[38]),"=r"((r)[39]), \
          "=r"((r)[40]),"=r"((r)[41]),"=r"((r)[42]),"=r"((r)[43]),"=r"((r)[44]),"=r"((r)[45]),"=r"((r)[46]),"=r"((r)[47]), \
          "=r"((r)[48]),"=r"((r)[49]),"=r"((r)[50]),"=r"((r)[51]),"=r"((r)[52]),"=r"((r)[53]),"=r"((r)[54]),"=r"((r)[55]), \
          "=r"((r)[56]),"=r"((r)[57]),"=r"((r)[58]),"=r"((r)[59]),"=r"((r)[60]),"=r"((r)[61]),"=r"((r)[62]),"=r"((r)[63]) \
        : "r"(a))
#define TC_ST_X32(a, r) \
    asm volatile("tcgen05.st.sync.aligned.32x32b.x32.b32 [%0], " \
        "{%1,%2,%3,%4,%5,%6,%7,%8,%9,%10,%11,%12,%13,%14,%15,%16," \
        "%17,%18,%19,%20,%21,%22,%23,%24,%25,%26,%27,%28,%29,%30,%31,%32};" \
        :: "r"(a), \
           "r"((r)[0]),"r"((r)[1]),"r"((r)[2]),"r"((r)[3]),"r"((r)[4]),"r"((r)[5]),"r"((r)[6]),"r"((r)[7]), \
           "r"((r)[8]),"r"((r)[9]),"r"((r)[10]),"r"((r)[11]),"r"((r)[12]),"r"((r)[13]),"r"((r)[14]),"r"((r)[15]), \
           "r"((r)[16]),"r"((r)[17]),"r"((r)[18]),"r"((r)[19]),"r"((r)[20]),"r"((r)[21]),"r"((r)[22]),"r"((r)[23]), \
           "r"((r)[24]),"r"((r)[25]),"r"((r)[26]),"r"((r)[27]),"r"((r)[28]),"r"((r)[29]),"r"((r)[30]),"r"((r)[31]) \
        : "memory")
#define IDESC_BF16 0x8400490u
__device__ __forceinline__ void mma_f16_ss(uint32_t d, uint64_t a, uint64_t b, bool en) {
    uint32_t e = en ? 1u : 0u;
    asm volatile("{\n\t.reg .pred p;\n\tsetp.ne.u32 p, %5, 0;\n\t"
        "tcgen05.mma.cta_group::1.kind::f16 [%0], %1, %2, %3, {%4,%4,%4,%4}, p;\n\t}"
        :: "r"(d), "l"(a), "l"(b), "r"(IDESC_BF16), "r"(0u), "r"(e) : "memory");
}
__device__ __forceinline__ void mma_f16_ts(uint32_t d, uint32_t a, uint64_t b, bool en) {
    uint32_t e = en ? 1u : 0u;
    asm volatile("{\n\t.reg .pred p;\n\tsetp.ne.u32 p, %5, 0;\n\t"
        "tcgen05.mma.cta_group::1.kind::f16 [%0], [%1], %2, %3, {%4,%4,%4,%4}, p;\n\t}"
        :: "r"(d), "r"(a), "l"(b), "r"(IDESC_BF16), "r"(0u), "r"(e) : "memory");
}
__device__ __forceinline__ uint64_t mk_desc(const void* p) {
    return 0x4000404000010000ULL | (ull)((smu32(p) >> 4) & 0x3FFF);
}
#endif

// ---------- generic fp32 GEMM (FFMA2); optional bf16-tile mirror ----------
#define GBM 64
#define GBN 64
#define GBK 16
__global__ void __launch_bounds__(256) gemm_kernel(
    const float* __restrict__ A0, int K0, const float* __restrict__ A1, int K1,
    const float* __restrict__ W, int ldw, const float* __restrict__ bias,
    float* __restrict__ C, int ldc, int M, int N, int mode,
    __nv_bfloat16* __restrict__ outT)
{
    __shared__ float As[GBK][GBM + 2];
    __shared__ float Wsm[GBK][GBN];
    const int tid = threadIdx.x, tx = tid & 15, ty = tid >> 4;
    const int row0 = blockIdx.x * GBM, col0 = blockIdx.y * GBN;
    const int K = K0 + K1;
    ull acc2[2][4] = {};
    for (int kt = 0; kt < K; kt += GBK) {
        {
            const int m = tid >> 2, kb = (tid & 3) * 4, gr = row0 + m;
            #pragma unroll
            for (int i = 0; i < 4; i++) {
                const int gk = kt + kb + i;
                float v = 0.0f;
                if (gk < K) v = (gk < K0) ? A0[(size_t)gr * K0 + gk] : A1[(size_t)gr * K1 + (gk - K0)];
                As[kb + i][m] = v;
            }
        }
        #pragma unroll
        for (int i = 0; i < 4; i++) {
            const int idx = tid + 256 * i, k = idx >> 6, n = idx & 63;
            const int gk = kt + k, gn = col0 + n;
            Wsm[k][n] = (gk < K && gn < N) ? W[(size_t)gk * ldw + gn] : 0.0f;
        }
        __syncthreads();
        #pragma unroll
        for (int k = 0; k < GBK; k++) {
            const ull a0 = *(const ull*)&As[k][ty * 4];
            const ull a1 = *(const ull*)&As[k][ty * 4 + 2];
            const float4 w4 = *(const float4*)&Wsm[k][tx * 4];
            ull wd[4] = {pack_dup(w4.x), pack_dup(w4.y), pack_dup(w4.z), pack_dup(w4.w)};
            #pragma unroll
            for (int j = 0; j < 4; j++) { fma2(acc2[0][j], a0, wd[j]); fma2(acc2[1][j], a1, wd[j]); }
        }
        __syncthreads();
    }
    #pragma unroll
    for (int i2 = 0; i2 < 2; i2++)
        #pragma unroll
        for (int j = 0; j < 4; j++) {
            float lo, hi; unpack2(acc2[i2][j], lo, hi);
            const int c = col0 + tx * 4 + j;
            if (c >= N) continue;
            float pair[2] = {lo, hi};
            #pragma unroll
            for (int u = 0; u < 2; u++) {
                const int r = row0 + ty * 4 + 2 * i2 + u;
                if (r >= M) continue;
                float v = pair[u];
                if (bias) v += bias[c];
                if (mode == 1) v = silu_f(v);
                C[(size_t)r * ldc + c] = v;
                if (outT) TILE_WR(outT, r, c, __float2bfloat16(v));
            }
        }
}

__global__ void timefeat_kernel(const float* __restrict__ t, float* __restrict__ feat)
{
    const int idx = blockIdx.x * blockDim.x + threadIdx.x;
    if (idx >= NODES * 128) return;
    const int node = idx >> 7, c = idx & 127, b = node >> 5;
    const float tv = t[b];
    const float kf = -logf(10000.0f) / 63.0f;
    float val = (c < 64) ? __sinf(tv * __expf((float)c * kf)) : __cosf(tv * __expf((float)(c - 64) * kf));
    feat[(size_t)node * 384 + 256 + c] = val;
}

__global__ void edgefeat_kernel(const float* __restrict__ frac, __nv_bfloat16* __restrict__ efT)
{
    const int idx = blockIdx.x * blockDim.x + threadIdx.x;
    if (idx >= NTILE * 128 * 64) return;
    const int tI = idx >> 13, rem = idx & 8191, r = rem >> 6, k = rem & 63;
    const int node = (tI << 2) + (r >> 5), j = r & 31, b = node >> 5;
    float val = 0.0f;
    if (k < 54) {
        const int a = (k < 27) ? k : (k - 27);
        const int dim = a / 9, f = a - dim * 9 + 1;
        float d = frac[(b * 32 + j) * 3 + dim] - frac[node * 3 + dim];
        d -= floorf(d);
        const float arg = d * (6.283185307179586f * (float)f);
        val = (k < 27) ? __sinf(arg) : __cosf(arg);
    }
    *(__nv_bfloat16*)((char*)efT + (size_t)tI * 16384 + sw128((uint32_t)(r * 128 + k * 2))) =
        __float2bfloat16(val);
}

__global__ void pack_w1t_kernel(const float* __restrict__ m1W, __nv_bfloat16* __restrict__ W1T)
{
    const int idx = blockIdx.x * blockDim.x + threadIdx.x;
    if (idx >= NLAY * 256 * 64) return;
    const int l = idx >> 14, rem = idx & 16383, n = rem >> 6, k = rem & 63;
    float v = 0.0f;
    if (k < 54) {
        const int a = (k < 27) ? k : (k - 27);
        const int dim = a / 9, f = a - dim * 9 + 1;
        const int row = 512 + ((k < 27) ? 0 : 30) + dim * 10 + f;
        v = m1W[(size_t)l * 578 * 256 + row * 256 + n];
    }
    *(__nv_bfloat16*)((char*)W1T + (size_t)l * 32768 + sw128((uint32_t)(n * 128 + k * 2))) =
        __float2bfloat16(v);
}

__global__ void pack_all_kernel(const float* __restrict__ m1W, const float* __restrict__ a1W,
                                const float* __restrict__ a2W, const float* __restrict__ m2W,
                                __nv_bfloat16* __restrict__ WB)
{
    const int idx = blockIdx.x * blockDim.x + threadIdx.x;
    if (idx >= 96 * 16384) return;
    const int chunk = idx >> 14, rem = idx & 16383, n = rem >> 6, kk = rem & 63;
    const int l = chunk / 24, cl = chunk - l * 24;
    const float* src; int k;
    if (cl < 4)       { src = m1W + (size_t)l * 578 * 256;         k = cl * 64 + kk; }
    else if (cl < 8)  { src = m1W + (size_t)l * 578 * 256 + 65536; k = (cl - 4) * 64 + kk; }
    else if (cl < 16) { src = a1W + (size_t)l * 512 * 256;         k = (cl - 8) * 64 + kk; }
    else if (cl < 20) { src = a2W + (size_t)l * 65536;             k = (cl - 16) * 64 + kk; }
    else              { src = m2W + (size_t)l * 65536;             k = (cl - 20) * 64 + kk; }
    *(__nv_bfloat16*)((char*)WB + (size_t)chunk * 32768 + sw128((uint32_t)(n * 128 + kk * 2)))
        = __float2bfloat16(src[(size_t)k * 256 + n]);
}

__global__ void prepq_kernel(const float* __restrict__ m1W, const float* __restrict__ m1b,
                             const float* __restrict__ lpolar, float* __restrict__ qb)
{
    const int l = blockIdx.x >> 7, gb = blockIdx.x & 127, c = threadIdx.x;
    const float* W1 = m1W + (size_t)l * 578 * 256;
    float q = m1b[l * 256 + c] + W1[542 * 256 + c] + W1[552 * 256 + c] + W1[562 * 256 + c];
    #pragma unroll
    for (int u = 0; u < 6; u++) q += lpolar[gb * 6 + u] * W1[(572 + u) * 256 + c];
    qb[((size_t)l * 128 + gb) * 256 + c] = q;
}

__global__ void layernorm_kernel(const float* __restrict__ x, const float* __restrict__ g,
                                 const float* __restrict__ b, float* __restrict__ yf)
{
    const int row = blockIdx.x, tid = threadIdx.x;
    const float v = x[(size_t)row * HID + tid];
    __shared__ float sr[8];
    float s = v;
    #pragma unroll
    for (int o = 16; o; o >>= 1) s += __shfl_xor_sync(~0u, s, o);
    if ((tid & 31) == 0) sr[tid >> 5] = s;
    __syncthreads();
    float tot = 0.0f;
    #pragma unroll
    for (int i = 0; i < 8; i++) tot += sr[i];
    const float mean = tot * (1.0f / 256.0f);
    const float d = v - mean;
    __syncthreads();
    float q = d * d;
    #pragma unroll
    for (int o = 16; o; o >>= 1) q += __shfl_xor_sync(~0u, q, o);
    if ((tid & 31) == 0) sr[tid >> 5] = q;
    __syncthreads();
    tot = 0.0f;
    #pragma unroll
    for (int i = 0; i < 8; i++) tot += sr[i];
    yf[(size_t)row * HID + tid] = d * rsqrtf(tot * (1.0f / 256.0f) + 1e-5f) * g[tid] + b[tid];
}

// ---------- fused LN + dual-P GEMM (layer 0 only) ----------
#define TG_SMEM 197632
__global__ void __launch_bounds__(256, 1) lnp_tc(
    const float* __restrict__ nf, const float* __restrict__ g, const float* __restrict__ b,
    const __nv_bfloat16* __restrict__ Wp, const float* __restrict__ qb,
    float* __restrict__ PiQ, float* __restrict__ PjT)
{
    extern __shared__ char smraw[];
    const int tid = threadIdx.x, t = blockIdx.x;
#if HAS_TC
    char* sb = (char*)(((uintptr_t)smraw + 1023) & ~(uintptr_t)1023);
    float* stage = (float*)(sb + 65536);
    __shared__ uint32_t s_tmem[1];
    __shared__ __align__(8) unsigned long long s_bar[1];
    const int wid = tid >> 5, lid = tid & 31;
    const uint32_t bar = smu32(&s_bar[0]);
    if (tid == 0) mbar_init(bar, 1);
    if (wid == 0)
        asm volatile("tcgen05.alloc.cta_group::1.sync.aligned.shared::cta.b32 [%0], 512;"
                     :: "r"(smu32(s_tmem)) : "memory");
    __syncthreads();
    const uint32_t tb = s_tmem[0];

    {
        const float4* gsrc = (const float4*)(nf + (size_t)t * 128 * 256);
        for (int i = tid; i < 8192; i += 256) cp16(((float4*)stage) + i, gsrc + i);
    }
    cp_commit(); cp_wait<0>();
    __syncthreads();

    {
        const int r = tid >> 1, h = tid & 1;
        const float4* rowp = (const float4*)(stage + r * 256 + h * 128);
        float s = 0.f, s2 = 0.f;
        #pragma unroll
        for (int q = 0; q < 32; q++) {
            const float4 v = rowp[q];
            s  += v.x + v.y + v.z + v.w;
            s2 += v.x * v.x + v.y * v.y + v.z * v.z + v.w * v.w;
        }
        s  += __shfl_xor_sync(~0u, s, 1);
        s2 += __shfl_xor_sync(~0u, s2, 1);
        const float mean = s * (1.0f / 256.0f);
        const float rstd = rsqrtf(s2 * (1.0f / 256.0f) - mean * mean + 1e-5f);
        #pragma unroll
        for (int q = 0; q < 32; q++) {
            const float4 v = rowp[q];
            const int cb = h * 128 + q * 4;
            const float4 gg = *(const float4*)(g + cb);
            const float4 bb = *(const float4*)(b + cb);
            const float rv[4] = {
                (v.x - mean) * rstd * gg.x + bb.x, (v.y - mean) * rstd * gg.y + bb.y,
                (v.z - mean) * rstd * gg.z + bb.z, (v.w - mean) * rstd * gg.w + bb.w };
            #pragma unroll
            for (int e = 0; e < 4; e++) {
                const int c = cb + e;
                *(__nv_bfloat16*)(sb + (c >> 6) * 16384
                    + sw128((uint32_t)((r << 7) + ((c & 63) << 1)))) = __float2bfloat16(rv[e]);
            }
        }
    }
    __syncthreads();

    #pragma unroll 1
    for (int p = 0; p < 2; p++) {
        const float4* gw = (const float4*)(Wp + (size_t)p * 4 * 16384);
        for (int i = tid; i < 8192; i += 256) cp16((float4*)(sb + 65536) + i, gw + i);
        cp_commit(); cp_wait<0>();
        fence_pa();
        __syncthreads();
        if (tid == 0) {
            const uint32_t d = tb + (p ? 256u : 0u);
            #pragma unroll
            for (int q = 0; q < 4; q++) {
                const uint64_t ad = mk_desc(sb + q * 16384);
                const uint64_t bd = mk_desc(sb + 65536 + q * 32768);
                #pragma unroll
                for (int s = 0; s < 4; s++) mma_f16_ss(d, ad + 2 * s, bd + 2 * s, q > 0 || s > 0);
            }
            tc_commit(bar);
        }
        mbar_wait(bar, (uint32_t)p);
        tcf_a();
        __syncthreads();
    }

    const int half = wid >> 2, sp = wid & 3;
    const int node = t * 128 + sp * 32 + lid;
    const int gb = node >> 5, jn = node & 31;
    #pragma unroll 1
    for (int i = 0; i < 2; i++) {
        const int c0 = half * 128 + 64 * i;
        uint32_t r0[64], r1[64];
        TC_LD_X64(r0, tb + c0);
        TC_LD_X64(r1, tb + 256 + c0);
        tcw_ld();
        #pragma unroll
        for (int c = 0; c < 64; c++) {
            const int gc = c0 + c;
            PiQ[(size_t)node * 256 + gc] = __uint_as_float(r0[c]) + qb[(size_t)gb * 256 + gc];
            PjT[((size_t)gb * 256 + gc) * 32 + jn] = __uint_as_float(r1[c]);
        }
    }
    __syncthreads();
    if (wid == 0) {
        asm volatile("tcgen05.relinquish_alloc_permit.cta_group::1.sync.aligned;");
        asm volatile("tcgen05.dealloc.cta_group::1.sync.aligned.b32 %0, 512;" :: "r"(tb));
    }
#else
    float* Xs = (float*)smraw;
    for (int idx = tid; idx < 128; idx += 256) {
        const int node = t * 128 + idx;
        float s = 0.f, s2 = 0.f;
        for (int c = 0; c < 256; c++) { float v = nf[(size_t)node * 256 + c]; s += v; s2 += v * v; }
        const float mean = s / 256.f, rstd = rsqrtf(s2 / 256.f - mean * mean + 1e-5f);
        for (int c = 0; c < 256; c++)
            Xs[idx * 256 + c] = __bfloat162float(__float2bfloat16(
                (nf[(size_t)node * 256 + c] - mean) * rstd * g[c] + b[c]));
    }
    __syncthreads();
    for (int m = 0; m < 128; m++) {
        const int node = t * 128 + m, c = tid, gb = node >> 5, jn = node & 31;
        float a0 = 0.f, a1v = 0.f;
        for (int k = 0; k < 256; k++) {
            const float a = Xs[m * 256 + k];
            const uint32_t off = sw128((uint32_t)(c * 128 + (k & 63) * 2));
            a0  += a * __bfloat162float(*(const __nv_bfloat16*)((const char*)Wp + (size_t)(k >> 6) * 32768 + off));
            a1v += a * __bfloat162float(*(const __nv_bfloat16*)((const char*)Wp + (size_t)(4 + (k >> 6)) * 32768 + off));
        }
        PiQ[(size_t)node * 256 + c] = a0 + qb[(size_t)gb * 256 + c];
        PjT[((size_t)gb * 256 + c) * 32 + jn] = a1v;
    }
#endif
}

// ---------- fused node update: a1 + a2 + residual + (LN + dual-P for next layer) ----------
__global__ void __launch_bounds__(256, 1) fused_node(
    const __nv_bfloat16* __restrict__ A0, const __nv_bfloat16* __restrict__ A1,
    const __nv_bfloat16* __restrict__ W1, const __nv_bfloat16* __restrict__ W2,
    const float* __restrict__ b1, const float* __restrict__ b2,
    float* __restrict__ nf, __nv_bfloat16* __restrict__ nfT,
    int doP, const float* __restrict__ g, const float* __restrict__ b,
    const __nv_bfloat16* __restrict__ Wp, const float* __restrict__ qbn,
    float* __restrict__ PiQ, float* __restrict__ PjT)
{
    extern __shared__ char smraw[];
    const int tid = threadIdx.x, t = blockIdx.x;
#if HAS_TC
    char* sb = (char*)(((uintptr_t)smraw + 1023) & ~(uintptr_t)1023);
    float* stage = (float*)(sb + 65536);
    __shared__ uint32_t s_tmem[1];
    __shared__ __align__(8) unsigned long long s_bar[1];
    const int wid = tid >> 5, lid = tid & 31;
    const uint32_t bar = smu32(&s_bar[0]);
    if (tid == 0) mbar_init(bar, 1);
    if (wid == 0)
        asm volatile("tcgen05.alloc.cta_group::1.sync.aligned.shared::cta.b32 [%0], 512;"
                     :: "r"(smu32(s_tmem)) : "memory");
    __syncthreads();
    const uint32_t tb = s_tmem[0];

    #pragma unroll 1
    for (int p = 0; p < 2; p++) {
        const __nv_bfloat16* Ac = p ? A1 : A0;
        const float4* ga = (const float4*)(Ac + (size_t)t * 4 * 8192);
        for (int i = tid; i < 4096; i += 256) cp16((float4*)sb + i, ga + i);
        const float4* gw = (const float4*)(W1 + (size_t)p * 4 * 16384);
        for (int i = tid; i < 8192; i += 256) cp16((float4*)(sb + 65536) + i, gw + i);
        cp_commit(); cp_wait<0>();
        fence_pa();
        __syncthreads();
        if (tid == 0) {
            #pragma unroll
            for (int q = 0; q < 4; q++) {
                const uint64_t ad = mk_desc(sb + q * 16384);
                const uint64_t bd = mk_desc(sb + 65536 + q * 32768);
                #pragma unroll
                for (int s = 0; s < 4; s++)
                    mma_f16_ss(tb, ad + 2 * s, bd + 2 * s, p > 0 || q > 0 || s > 0);
            }
            tc_commit(bar);
        }
        mbar_wait(bar, (uint32_t)p);
        tcf_a();
        __syncthreads();
    }

    {
        const float4* gw = (const float4*)W2;
        for (int i = tid; i < 8192; i += 256) cp16((float4*)(sb + 65536) + i, gw + i);
        cp_commit();
    }

    const int half = wid >> 2, sp = wid & 3;
    const int node = t * 128 + sp * 32 + lid;
    const int m = sp * 32 + lid;

    #pragma unroll 1
    for (int i = 0; i < 2; i++) {
        const int c0 = half * 128 + 64 * i;
        uint32_t r[64];
        TC_LD_X64(r, tb + c0);
        float bb[64];
        #pragma unroll
        for (int u = 0; u < 16; u++) *(float4*)&bb[4 * u] = ((const float4*)(b1 + c0))[u];
        tcw_ld();
        float v[64];
        #pragma unroll
        for (int c = 0; c < 64; c++) v[c] = silu_t(__uint_as_float(r[c]) + bb[c]);
        uint32_t xp[32];
        #pragma unroll
        for (int p = 0; p < 32; p++)
            asm("cvt.rn.bf16x2.f32 %0, %1, %2;" : "=r"(xp[p]) : "f"(v[2 * p + 1]), "f"(v[2 * p]));
        TC_ST_X32(tb + 256 + half * 64 + 32 * i + ((uint32_t)sp << 21), xp);
    }
    tcw_st();
    tcf_b();
    cp_wait<0>();
    fence_pa();
    __syncthreads();

    if (tid == 0) {
        tcf_a();
        const uint64_t bd = mk_desc(sb + 65536);
        #pragma unroll
        for (int s = 0; s < 16; s++)
            mma_f16_ts(tb, tb + 256 + 8 * s, bd + (uint64_t)((s >> 2) * 2048 + (s & 3) * 2), s > 0);
        tc_commit(bar);
    }
    mbar_wait(bar, 0u);
    tcf_a();

    #pragma unroll 1
    for (int i = 0; i < 2; i++) {
        const int c0 = half * 128 + 64 * i;
        uint32_t r[64];
        TC_LD_X64(r, tb + c0);
        float bb[64];
        #pragma unroll
        for (int u = 0; u < 16; u++) *(float4*)&bb[4 * u] = ((const float4*)(b2 + c0))[u];
        tcw_ld();
        #pragma unroll
        for (int c = 0; c < 64; c++) {
            const int gc = c0 + c;
            const float nv = nf[(size_t)node * 256 + gc] + silu_t(__uint_as_float(r[c]) + bb[c]);
            nf[(size_t)node * 256 + gc] = nv;
            TILE_WR(nfT, node, gc, __float2bfloat16(nv));
            if (doP) stage[m * 256 + gc] = nv;
        }
    }
    tcf_b();
    __syncthreads();

    if (doP) {
        {
            const int r = tid >> 1, h = tid & 1;
            const float4* rowp = (const float4*)(stage + r * 256 + h * 128);
            float s = 0.f, s2 = 0.f;
            #pragma unroll
            for (int q = 0; q < 32; q++) {
                const float4 v = rowp[q];
                s  += v.x + v.y + v.z + v.w;
                s2 += v.x * v.x + v.y * v.y + v.z * v.z + v.w * v.w;
            }
            s  += __shfl_xor_sync(~0u, s, 1);
            s2 += __shfl_xor_sync(~0u, s2, 1);
            const float mean = s * (1.0f / 256.0f);
            const float rstd = rsqrtf(s2 * (1.0f / 256.0f) - mean * mean + 1e-5f);
            #pragma unroll
            for (int q = 0; q < 32; q++) {
                const float4 v = rowp[q];
                const int cb = h * 128 + q * 4;
                const float4 gg = *(const float4*)(g + cb);
                const float4 bbv = *(const float4*)(b + cb);
                const float rv[4] = {
                    (v.x - mean) * rstd * gg.x + bbv.x, (v.y - mean) * rstd * gg.y + bbv.y,
                    (v.z - mean) * rstd * gg.z + bbv.z, (v.w - mean) * rstd * gg.w + bbv.w };
                #pragma unroll
                for (int e = 0; e < 4; e++) {
                    const int c = cb + e;
                    *(__nv_bfloat16*)(sb + (c >> 6) * 16384
                        + sw128((uint32_t)((r << 7) + ((c & 63) << 1)))) = __float2bfloat16(rv[e]);
                }
            }
        }
        __syncthreads();

        #pragma unroll 1
        for (int p = 0; p < 2; p++) {
            const float4* gw = (const float4*)(Wp + (size_t)p * 4 * 16384);
            for (int i = tid; i < 8192; i += 256) cp16((float4*)(sb + 65536) + i, gw + i);
            cp_commit(); cp_wait<0>();
            fence_pa();
            __syncthreads();
            if (tid == 0) {
                tcf_a();
                const uint32_t d = tb + (p ? 256u : 0u);
                #pragma unroll
                for (int q = 0; q < 4; q++) {
                    const uint64_t ad = mk_desc(sb + q * 16384);
                    const uint64_t bd = mk_desc(sb + 65536 + q * 32768);
                    #pragma unroll
                    for (int s = 0; s < 4; s++) mma_f16_ss(d, ad + 2 * s, bd + 2 * s, q > 0 || s > 0);
                }
                tc_commit(bar);
            }
            mbar_wait(bar, (uint32_t)(p ? 0 : 1));
            tcf_a();
            __syncthreads();
        }

        const int gb = node >> 5, jn = node & 31;
        #pragma unroll 1
        for (int i = 0; i < 2; i++) {
            const int c0 = half * 128 + 64 * i;
            uint32_t r0[64], r1[64];
            TC_LD_X64(r0, tb + c0);
            TC_LD_X64(r1, tb + 256 + c0);
            tcw_ld();
            #pragma unroll
            for (int c = 0; c < 64; c++) {
                const int gc = c0 + c;
                PiQ[(size_t)node * 256 + gc] = __uint_as_float(r0[c]) + qbn[(size_t)gb * 256 + gc];
                PjT[((size_t)gb * 256 + gc) * 32 + jn] = __uint_as_float(r1[c]);
            }
        }
    }
    __syncthreads();
    if (wid == 0) {
        asm volatile("tcgen05.relinquish_alloc_permit.cta_group::1.sync.aligned;");
        asm volatile("tcgen05.dealloc.cta_group::1.sync.aligned.b32 %0, 512;" :: "r"(tb));
    }
#else
    float* Xs = (float*)smraw;
    for (int m2 = 0; m2 < 128; m2++) {
        const int node = t * 128 + m2, c = tid;
        float acc = b1[c];
        for (int k = 0; k < 512; k++) {
            const __nv_bfloat16* At = (k < 256) ? A0 : A1;
            const int kk = k & 255;
            float a = __bfloat162float(*(const __nv_bfloat16*)((const char*)At
                        + (size_t)((t << 2) + (kk >> 6)) * 16384
                        + sw128((uint32_t)((m2 << 7) + ((kk & 63) << 1)))));
            float w = __bfloat162float(*(const __nv_bfloat16*)((const char*)W1
                        + (size_t)(k >> 6) * 32768 + sw128((uint32_t)(c * 128 + (k & 63) * 2))));
            acc += a * w;
        }
        Xs[m2 * 256 + c] = __bfloat162float(__float2bfloat16(silu_f(acc)));
        __syncthreads();
    }
    for (int m2 = 0; m2 < 128; m2++) {
        const int node = t * 128 + m2, c = tid;
        float acc = b2[c];
        for (int k = 0; k < 256; k++)
            acc += Xs[m2 * 256 + k] * __bfloat162float(*(const __nv_bfloat16*)((const char*)W2
                    + (size_t)(k >> 6) * 32768 + sw128((uint32_t)(c * 128 + (k & 63) * 2))));
        const float nv = nf[(size_t)node * 256 + c] + silu_f(acc);
        nf[(size_t)node * 256 + c] = nv;
        TILE_WR(nfT, node, c, __float2bfloat16(nv));
    }
    __syncthreads();
    if (doP) {
        for (int m2 = 0; m2 < 128; m2++) {
            const int node = t * 128 + m2;
            if (tid == 0) {
                float s = 0.f, s2 = 0.f;
                for (int c = 0; c < 256; c++) { float v = nf[(size_t)node * 256 + c]; s += v; s2 += v * v; }
                Xs[m2 * 256] = s / 256.f;
                Xs[m2 * 256 + 1] = rsqrtf(s2 / 256.f - (s / 256.f) * (s / 256.f) + 1e-5f);
            }
            __syncthreads();
            const float mean = Xs[m2 * 256], rstd = Xs[m2 * 256 + 1];
            const float hv = __bfloat162float(__float2bfloat16(
                (nf[(size_t)node * 256 + tid] - mean) * rstd * g[tid] + b[tid]));
            __syncthreads();
            Xs[m2 * 256 + tid] = hv;
            __syncthreads();
        }
        for (int m2 = 0; m2 < 128; m2++) {
            const int node = t * 128 + m2, c = tid, gb = node >> 5, jn = node & 31;
            float a0 = 0.f, a1v = 0.f;
            for (int k = 0; k < 256; k++) {
                const float a = Xs[m2 * 256 + k];
                const uint32_t off = sw128((uint32_t)(c * 128 + (k & 63) * 2));
                a0  += a * __bfloat162float(*(const __nv_bfloat16*)((const char*)Wp + (size_t)(k >> 6) * 32768 + off));
                a1v += a * __bfloat162float(*(const __nv_bfloat16*)((const char*)Wp + (size_t)(4 + (k >> 6)) * 32768 + off));
            }
            PiQ[(size_t)node * 256 + c] = a0 + qbn[(size_t)gb * 256 + c];
            PjT[((size_t)gb * 256 + c) * 32 + jn] = a1v;
        }
    }
#endif
}

// ---------- fused edge kernel (x64 LDTM) ----------
#define EDGE_SMEM_REQ 230400
__global__ void __launch_bounds__(256, 1) edge_msg_tc(
    const float* __restrict__ PiQ, const float* __restrict__ PjT,
    const __nv_bfloat16* __restrict__ efT, const __nv_bfloat16* __restrict__ W1T,
    const __nv_bfloat16* __restrict__ W2T, const float* __restrict__ b2,
    __nv_bfloat16* __restrict__ msgT)
{
    extern __shared__ char smraw[];
#if HAS_TC
    char* sb = (char*)(((uintptr_t)smraw + 1023) & ~(uintptr_t)1023);
    float* Pjs = (float*)(sb + 65536);
    __shared__ uint32_t s_tmem[1];
    __shared__ __align__(8) unsigned long long s_bar[2];

    const int tid = threadIdx.x, wid = tid >> 5, lid = tid & 31;
    const int gb = blockIdx.x;
    const uint32_t barE = smu32(&s_bar[0]), barY = smu32(&s_bar[1]);

    if (tid == 0) { mbar_init(barE, 1); mbar_init(barY, 1); }
    if (wid == 0)
        asm volatile("tcgen05.alloc.cta_group::1.sync.aligned.shared::cta.b32 [%0], 512;"
                     :: "r"(smu32(s_tmem)) : "memory");
    __syncthreads();
    const uint32_t tb = s_tmem[0];

    {
        const float4* g = (const float4*)efT + (size_t)gb * 8192;
        for (int i = tid; i < 1024; i += 256) cp16((float4*)sb + i, g + i);
    }
    cp_commit();
    {
        const float4* g1 = (const float4*)W1T;
        for (int i = tid; i < 2048; i += 256) cp16((float4*)(sb + 32768) + i, g1 + i);
        const float4* gp = (const float4*)(PjT + (size_t)gb * 8192);
        for (int i = tid; i < 2048; i += 256) cp16((float4*)(sb + 65536) + i, gp + i);
        const float4* g2 = (const float4*)W2T;
        for (int i = tid; i < 8192; i += 256) cp16((float4*)(sb + 98304) + i, g2 + i);
    }
    cp_commit();
    {
        const float4* g = (const float4*)efT + (size_t)gb * 8192 + 1024;
        for (int i = tid; i < 1024; i += 256) cp16((float4*)(sb + 16384) + i, g + i);
    }
    cp_commit();

    const uint64_t w1d = mk_desc(sb + 32768);
    const uint64_t w2d = mk_desc(sb + 98304);
    const int half = wid >> 2, nodeL = wid & 3;

    #pragma unroll 1
    for (int t = 0; t < 8; t++) {
        char* efb = sb + (t & 1) * 16384;
        const int node = gb * 32 + 4 * t + nodeL;
        const uint32_t ph = (uint32_t)(t & 1);

        cp_wait<1>();
        fence_pa();
        __syncthreads();
        if (tid == 0) {
            const uint64_t ad = mk_desc(efb);
            #pragma unroll
            for (int s = 0; s < 4; s++) mma_f16_ss(tb, ad + 2 * s, w1d + 2 * s, s > 0);
            tc_commit(barE);
        }
        mbar_wait(barE, ph);
        tcf_a();
        if (t < 6) {
            const float4* g = (const float4*)efT + (size_t)(gb * 8 + t + 2) * 1024;
            for (int i = tid; i < 1024; i += 256) cp16((float4*)efb + i, g + i);
        }
        cp_commit();

        const float* piqp = PiQ + (size_t)node * 256;
        #pragma unroll 1
        for (int i = 0; i < 2; i++) {
            const int c0 = half * 128 + 64 * i;
            uint32_t r[64];
            TC_LD_X64(r, tb + c0);
            float piq[64];
            #pragma unroll
            for (int u = 0; u < 16; u++) *(float4*)&piq[4 * u] = ((const float4*)(piqp + c0))[u];
            tcw_ld();
            float v[64];
            #pragma unroll
            for (int c = 0; c < 64; c++)
                v[c] = silu_t(__uint_as_float(r[c]) + piq[c] + Pjs[(c0 + c) * 32 + lid]);
            uint32_t xp[32];
            #pragma unroll
            for (int p = 0; p < 32; p++)
                asm("cvt.rn.bf16x2.f32 %0, %1, %2;" : "=r"(xp[p]) : "f"(v[2 * p + 1]), "f"(v[2 * p]));
            TC_ST_X32(tb + 384 + half * 64 + 32 * i + ((uint32_t)nodeL << 21), xp);
        }
        tcw_st();
        tcf_b();
        __syncthreads();

        if (tid == 0) {
            tcf_a();
            #pragma unroll
            for (int s = 0; s < 16; s++)
                mma_f16_ts(tb, tb + 384 + 8 * s, w2d + (uint64_t)((s >> 2) * 2048 + (s & 3) * 2), s > 0);
            tc_commit(barY);
        }
        mbar_wait(barY, ph);
        tcf_a();

        #pragma unroll 1
        for (int i = 0; i < 2; i++) {
            const int c0 = half * 128 + 64 * i;
            uint32_t r[64];
            TC_LD_X64(r, tb + c0);
            float bb[64];
            #pragma unroll
            for (int u = 0; u < 16; u++) *(float4*)&bb[4 * u] = ((const float4*)(b2 + c0))[u];
            tcw_ld();
            float v[64];
            #pragma unroll
            for (int c = 0; c < 64; c++) v[c] = silu_t(__uint_as_float(r[c]) + bb[c]);
            #pragma unroll
            for (int off = 16; off; off >>= 1) {
                const bool hi = (lid & off) != 0;
                #pragma unroll
                for (int k = 0; k < off; k++) {
                    float s0 = hi ? v[k] : v[k + off];
                    float rc0 = __shfl_xor_sync(~0u, s0, off);
                    float k0 = hi ? v[k + off] : v[k];
                    v[k] = k0 + rc0;
                    float s1 = hi ? v[32 + k] : v[32 + k + off];
                    float rc1 = __shfl_xor_sync(~0u, s1, off);
                    float k1 = hi ? v[32 + k + off] : v[32 + k];
                    v[32 + k] = k1 + rc1;
                }
            }
            TILE_WR(msgT, node, c0 + lid, __float2bfloat16(v[0] * 0.03125f));
            TILE_WR(msgT, node, c0 + 32 + lid, __float2bfloat16(v[32] * 0.03125f));
        }
        __syncthreads();
    }

    if (wid == 0) {
        asm volatile("tcgen05.relinquish_alloc_permit.cta_group::1.sync.aligned;");
        asm volatile("tcgen05.dealloc.cta_group::1.sync.aligned.b32 %0, 512;" :: "r"(tb));
    }
#else
    float* Xf = (float*)smraw;
    const int tid = threadIdx.x, gb = blockIdx.x;
    for (int nl = 0; nl < 32; nl++) {
        const int node = gb * 32 + nl;
        const int tI = node >> 2, rb = (node & 3) * 32;
        for (int idx = tid; idx < 32 * 256; idx += 256) {
            const int j = idx >> 8, c = idx & 255;
            const int r = rb + j;
            float e = 0.f;
            for (int k = 0; k < 54; k++) {
                float a = __bfloat162float(*(const __nv_bfloat16*)((const char*)efT
                            + (size_t)tI * 16384 + sw128((uint32_t)(r * 128 + k * 2))));
                float w = __bfloat162float(*(const __nv_bfloat16*)((const char*)W1T
                            + sw128((uint32_t)(c * 128 + k * 2))));
                e += a * w;
            }
            e += PiQ[(size_t)node * 256 + c] + PjT[((size_t)(gb * 256 + c)) * 32 + j];
            Xf[j * 260 + c] = silu_f(e);
        }
        __syncthreads();
        const int c = tid;
        float acc = 0.f;
        for (int j = 0; j < 32; j++) {
            float y = b2[c];
            for (int k = 0; k < 256; k++) {
                const size_t byte = (size_t)(k >> 6) * 32768 + (c >> 3) * 1024
                                  + sw128((uint32_t)((c & 7) * 128 + (k & 63) * 2));
                y += Xf[j * 260 + k] * __bfloat162float(*(const __nv_bfloat16*)((const char*)W2T + byte));
            }
            acc += silu_f(y);
        }
        TILE_WR(msgT, node, c, __float2bfloat16(acc * (1.0f / 32.0f)));
        __syncthreads();
    }
#endif
}

__global__ void graphmean_kernel(const float* __restrict__ h, float* __restrict__ gf)
{
    const int b = blockIdx.x, c = threadIdx.x;
    float s = 0.0f;
    #pragma unroll
    for (int i = 0; i < 32; i++) s += h[(size_t)((b << 5) + i) * HID + c];
    gf[(size_t)b * HID + c] = s * (1.0f / 32.0f);
}

static void run_gemm(cudaStream_t s, const float* A0, int K0, const float* A1, int K1,
                     const float* W, int ldw, const float* bias,
                     float* C, int ldc, int M, int N, int mode,
                     __nv_bfloat16* outT = nullptr)
{
    dim3 grid((M + GBM - 1) / GBM, (N + GBN - 1) / GBN);
    gemm_kernel<<<grid, 256, 0, s>>>(A0, K0, A1, K1, W, ldw, bias, C, ldc, M, N, mode, outT);
}

extern "C" void kernel_launch(void* const* d_in, const int* in_sizes, int n_in,
                              void* d_out, int out_size)
{
    const float* t          = (const float*)d_in[0];
    const float* atom_types = (const float*)d_in[1];
    const float* frac       = (const float*)d_in[2];
    const float* l_polar    = (const float*)d_in[3];
    const float* Ws      = (const float*)d_in[5];
    const float* bs      = (const float*)d_in[6];
    const float* Wn      = (const float*)d_in[7];
    const float* bn      = (const float*)d_in[8];
    const float* ln_g    = (const float*)d_in[9];
    const float* ln_b    = (const float*)d_in[10];
    const float* m1_W    = (const float*)d_in[11];
    const float* m1_b    = (const float*)d_in[12];
    const float* m2_W    = (const float*)d_in[13];
    const float* m2_b    = (const float*)d_in[14];
    const float* a1_W    = (const float*)d_in[15];
    const float* a1_b    = (const float*)d_in[16];
    const float* a2_W    = (const float*)d_in[17];
    const float* a2_b    = (const float*)d_in[18];
    const float* fln_g   = (const float*)d_in[19];
    const float* fln_b   = (const float*)d_in[20];
    const float* type_W  = (const float*)d_in[21];
    const float* type_b  = (const float*)d_in[22];
    const float* polar_W = (const float*)d_in[23];
    const float* frac_W  = (const float*)d_in[24];
    float* out = (float*)d_out;

    float *feat, *nf, *h, *PiQ, *PjT, *gf, *qb;
    __nv_bfloat16 *efT, *W1T, *WB, *nfT, *msgT;
    cudaGetSymbolAddress((void**)&feat, g_feat);
    cudaGetSymbolAddress((void**)&nf,   g_nf);
    cudaGetSymbolAddress((void**)&h,    g_h);
    cudaGetSymbolAddress((void**)&PiQ,  g_PiQ);
    cudaGetSymbolAddress((void**)&PjT,  g_PjT);
    cudaGetSymbolAddress((void**)&gf,   g_gf);
    cudaGetSymbolAddress((void**)&qb,   g_qb);
    cudaGetSymbolAddress((void**)&efT,  g_efT);
    cudaGetSymbolAddress((void**)&W1T,  g_W1T);
    cudaGetSymbolAddress((void**)&WB,   g_WB);
    cudaGetSymbolAddress((void**)&nfT,  g_nfT);
    cudaGetSymbolAddress((void**)&msgT, g_msgT);

    cudaFuncSetAttribute(edge_msg_tc, cudaFuncAttributeMaxDynamicSharedMemorySize, EDGE_SMEM_REQ);
    cudaFuncSetAttribute(lnp_tc, cudaFuncAttributeMaxDynamicSharedMemorySize, TG_SMEM);
    cudaFuncSetAttribute(fused_node, cudaFuncAttributeMaxDynamicSharedMemorySize, TG_SMEM);

    static cudaStream_t s2 = nullptr;
    static cudaEvent_t ev0, ev1, ev2, ev3;
    if (!s2) {
        cudaStreamCreateWithFlags(&s2, cudaStreamNonBlocking);
        cudaEventCreateWithFlags(&ev0, cudaEventDisableTiming);
        cudaEventCreateWithFlags(&ev1, cudaEventDisableTiming);
        cudaEventCreateWithFlags(&ev2, cudaEventDisableTiming);
        cudaEventCreateWithFlags(&ev3, cudaEventDisableTiming);
    }
    cudaStream_t s = 0;

    cudaEventRecord(ev0, s);
    cudaStreamWaitEvent(s2, ev0, 0);
    edgefeat_kernel<<<(NTILE * 128 * 64) / 256, 256, 0, s2>>>(frac, efT);
    pack_w1t_kernel<<<(NLAY * 256 * 64) / 256, 256, 0, s2>>>(m1_W, W1T);
    pack_all_kernel<<<(96 * 16384) / 256, 256, 0, s2>>>(m1_W, a1_W, a2_W, m2_W, WB);
    prepq_kernel<<<NLAY * BGR, 256, 0, s2>>>(m1_W, m1_b, l_polar, qb);
    cudaEventRecord(ev1, s2);

    timefeat_kernel<<<(NODES * 128 + 255) / 256, 256, 0, s>>>(t, feat);
    run_gemm(s, atom_types, TYPED, nullptr, 0, Ws, HID, bs, feat, 384, NODES, HID, 0);
    run_gemm(s, feat, 384, nullptr, 0, Wn, HID, bn, nf, HID, NODES, HID, 0, nfT);
    cudaStreamWaitEvent(s, ev1, 0);

    lnp_tc<<<32, 256, TG_SMEM, s>>>(nf, ln_g, ln_b, WB, qb, PiQ, PjT);

    for (int l = 0; l < NLAY; l++) {
        __nv_bfloat16* WL = WB + (size_t)l * 24 * 16384;
        edge_msg_tc<<<BGR, 256, EDGE_SMEM_REQ, s>>>(
            PiQ, PjT, efT, W1T + (size_t)l * 16384, WL + 20 * 16384, m2_b + l * HID, msgT);
        const int doP = (l < NLAY - 1) ? 1 : 0;
        const int ln = doP ? (l + 1) : 0;
        fused_node<<<32, 256, TG_SMEM, s>>>(
            nfT, msgT, WL + 8 * 16384, WL + 16 * 16384,
            a1_b + l * HID, a2_b + l * HID, nf, nfT,
            doP, ln_g + ln * HID, ln_b + ln * HID,
            WB + (size_t)ln * 24 * 16384, qb + (size_t)ln * BGR * HID, PiQ, PjT);
    }

    layernorm_kernel<<<NODES, 256, 0, s>>>(nf, fln_g, fln_b, h);

    cudaEventRecord(ev2, s);
    cudaStreamWaitEvent(s2, ev2, 0);
    run_gemm(s2, h, HID, nullptr, 0, frac_W, 3, nullptr,
             out + (size_t)NODES * TYPED + (size_t)BGR * 6, 3, NODES, 3, 0);
    cudaEventRecord(ev3, s2);

    graphmean_kernel<<<BGR, 256, 0, s>>>(h, gf);
    run_gemm(s, gf, HID, nullptr, 0, polar_W, 6, nullptr, out + (size_t)NODES * TYPED, 6, BGR, 6, 0);
    run_gemm(s, h, HID, nullptr, 0, type_W, TYPED, type_b, out, TYPED, NODES, TYPED, 0);
    cudaStreamWaitEvent(s, ev3, 0);
}